// round 4
// baseline (speedup 1.0000x reference)
#include <cuda_runtime.h>
#include <cuda_fp16.h>
#include <stdint.h>

#define B 4
#define S 2048
#define H 8
#define E 64
#define BH (B*H)
#define PADQ 72    // Q/K smem row stride (halves)
#define PADV 136   // V/attn smem row stride (halves)

// ---------------------------------------------------------------------------
// Device scratch (allocation-free)
// ---------------------------------------------------------------------------
__device__ __half g_qh[(size_t)BH*S*E];   // fp16 hi of 0.125*Qproj [bh][s][e]
__device__ __half g_ql[(size_t)BH*S*E];
__device__ __half g_kh[(size_t)BH*S*E];   // [bh][s][e]
__device__ __half g_kl[(size_t)BH*S*E];
__device__ __half g_vh[(size_t)BH*E*S];   // transposed [bh][e][s]
__device__ __half g_vl[(size_t)BH*E*S];

// ---------------------------------------------------------------------------
// MMA helpers (baseline PTX, works at .target sm_103)
// ---------------------------------------------------------------------------
__device__ __forceinline__ uint32_t smem_to_u32(const void* p) {
    uint32_t a;
    asm("{ .reg .u64 t; cvta.to.shared.u64 t, %1; cvt.u32.u64 %0, t; }" : "=r"(a) : "l"(p));
    return a;
}
#define LDSM_X4(R0, R1, R2, R3, ADDR) \
    asm volatile("ldmatrix.sync.aligned.m8n8.x4.shared.b16 {%0,%1,%2,%3}, [%4];" \
                 : "=r"(R0), "=r"(R1), "=r"(R2), "=r"(R3) : "r"(ADDR))
#define MMA16816(C, A0, A1, A2, A3, B0, B1) \
    asm volatile("mma.sync.aligned.m16n8k16.row.col.f32.f16.f16.f32 " \
                 "{%0,%1,%2,%3}, {%4,%5,%6,%7}, {%8,%9}, {%0,%1,%2,%3};" \
                 : "+f"((C)[0]), "+f"((C)[1]), "+f"((C)[2]), "+f"((C)[3]) \
                 : "r"(A0), "r"(A1), "r"(A2), "r"(A3), "r"(B0), "r"(B1))

// ---------------------------------------------------------------------------
// Threefry2x32 (JAX partitionable) — validated rounds 1/3
// ---------------------------------------------------------------------------
__device__ __forceinline__ uint32_t rotl32(uint32_t v, int s) { return __funnelshift_l(v, v, s); }
__device__ __forceinline__ uint32_t threefry_mask_bits(uint32_t idx) {
    const uint32_t ks0 = 0u, ks1 = 42u, ks2 = 0x1BD11BDAu ^ 42u;
    uint32_t x0 = ks0, x1 = idx + ks1;
#define TFR(r) { x0 += x1; x1 = rotl32(x1, r); x1 ^= x0; }
    TFR(13) TFR(15) TFR(26) TFR(6)
    x0 += ks1; x1 += ks2 + 1u;
    TFR(17) TFR(29) TFR(16) TFR(24)
    x0 += ks2; x1 += ks0 + 2u;
    TFR(13) TFR(15) TFR(26) TFR(6)
    x0 += ks0; x1 += ks1 + 3u;
    TFR(17) TFR(29) TFR(16) TFR(24)
    x0 += ks1; x1 += ks2 + 4u;
    TFR(13) TFR(15) TFR(26) TFR(6)
    x0 += ks2; x1 += ks0 + 5u;
#undef TFR
    return x0 ^ x1;
}
#define KEEP_THRESH (7549747u << 9)

// ---------------------------------------------------------------------------
// Kernel 1: QKV projection -> fp16 hi/lo (Q scaled 0.125, V transposed)
// ---------------------------------------------------------------------------
#define PROJ_TOK 32

__global__ __launch_bounds__(256) void proj_kernel(
    const float* __restrict__ qin, const float* __restrict__ kin, const float* __restrict__ vin,
    const float* __restrict__ Wq, const float* __restrict__ bq,
    const float* __restrict__ Wk, const float* __restrict__ bk,
    const float* __restrict__ Wv, const float* __restrict__ bv)
{
    __shared__ float sW[64][68];
    __shared__ float sb[64];
    __shared__ float sx[PROJ_TOK][64];

    const int m = blockIdx.y;
    const float* __restrict__ xin  = (m == 0) ? qin : ((m == 1) ? kin : vin);
    const float* __restrict__ W    = (m == 0) ? Wq  : ((m == 1) ? Wk  : Wv);
    const float* __restrict__ bias = (m == 0) ? bq  : ((m == 1) ? bk  : bv);

    const int tid = threadIdx.x;
    const size_t tok0 = (size_t)blockIdx.x * PROJ_TOK;

    for (int i = tid; i < 64 * 16; i += 256) {
        int r = i >> 4, c = i & 15;
        ((float4*)(&sW[r][0]))[c] = ((const float4*)W)[i];
    }
    if (tid < 64) sb[tid] = bias[tid];
    for (int i = tid; i < PROJ_TOK * 16; i += 256)
        ((float4*)(&sx[0][0]))[i] = ((const float4*)(xin + tok0 * 64))[i];
    __syncthreads();

    const int f  = tid & 63;
    const int tg = tid >> 6;

    float4 wr[16];
    #pragma unroll
    for (int e4 = 0; e4 < 16; e4++) wr[e4] = ((float4*)(&sW[f][0]))[e4];
    const float bsv = sb[f];

    for (int tt = 0; tt < PROJ_TOK; tt += 4) {
        const int t = tt + tg;
        float acc = bsv;
        #pragma unroll
        for (int e4 = 0; e4 < 16; e4++) {
            float4 xv = ((float4*)(&sx[t][0]))[e4];
            acc += xv.x * wr[e4].x + xv.y * wr[e4].y + xv.z * wr[e4].z + xv.w * wr[e4].w;
        }
        const size_t tok = tok0 + t;
        const int b   = (int)(tok >> 14);
        const int rem = (int)(tok & 16383);
        const int s   = rem >> 3;
        const int hh  = rem & 7;
        const size_t bh = (size_t)(b * H + hh);

        float a = (m == 0) ? acc * 0.125f : acc;
        __half hi = __float2half_rn(a);
        __half lo = __float2half_rn(a - __half2float(hi));
        if (m == 0) {
            size_t o = (bh * S + s) * 64 + f;
            g_qh[o] = hi; g_ql[o] = lo;
        } else if (m == 1) {
            size_t o = (bh * S + s) * 64 + f;
            g_kh[o] = hi; g_kl[o] = lo;
        } else {
            size_t o = (bh * 64 + f) * S + s;
            g_vh[o] = hi; g_vl[o] = lo;
        }
    }
}

// ---------------------------------------------------------------------------
// Kernel 2: fused flash attention (exact two-pass softmax + dropout + PV)
// CTA: 128 q-rows of one bh.  8 warps.
// Scores warps: 4(q) x 2(k), warp tile 32q x 64k.
// PV warps:     4(q) x 2(e), warp tile 32q x 32e.
// ---------------------------------------------------------------------------
#define NCHUNK 16   // 2048 / 128

__global__ __launch_bounds__(256, 1) void flash_kernel(float* __restrict__ out)
{
    extern __shared__ char smraw[];
    __half* sQH = (__half*)smraw;            // [128][PADQ]
    __half* sQL = sQH + 128 * PADQ;
    __half* sKH = sQL + 128 * PADQ;          // [128][PADQ]
    __half* sKL = sKH + 128 * PADQ;
    __half* sVH = sKL + 128 * PADQ;          // [64][PADV]
    __half* sVL = sVH + 64 * PADV;
    __half* sAT = sVL + 64 * PADV;           // [128][PADV]
    float*  sM  = (float*)(sAT + 128 * PADV);// [128]
    float*  sL  = sM + 128;                  // [128]
    float*  sP0 = sL + 128;                  // [128] partials (warp-pair 0)
    float*  sP1 = sP0 + 128;                 // [128] partials (warp-pair 1)
    float*  sInv = sP1 + 128;                // [128] 1/l

    const int tid = threadIdx.x;
    const int q0 = blockIdx.x * 128, bh = blockIdx.y;

    const __half* qhp = g_qh + ((size_t)bh * S + q0) * 64;
    const __half* qlp = g_ql + ((size_t)bh * S + q0) * 64;
    const __half* khp = g_kh + (size_t)bh * S * 64;
    const __half* klp = g_kl + (size_t)bh * S * 64;
    const __half* vhp = g_vh + (size_t)bh * 64 * S;
    const __half* vlp = g_vl + (size_t)bh * 64 * S;

    // load Q once
    for (int i = tid; i < 1024; i += 256) {
        int r = i >> 3, c = (i & 7) * 8;
        *(uint4*)(sQH + r * PADQ + c) = *(const uint4*)(qhp + r * 64 + c);
        *(uint4*)(sQL + r * PADQ + c) = *(const uint4*)(qlp + r * 64 + c);
    }
    if (tid < 128) { sM[tid] = -1e30f; sL[tid] = 0.0f; }

    const int w = tid >> 5, lane = tid & 31;
    const int qrow0 = (w >> 1) * 32, kcol0 = (w & 1) * 64;
    const int lr = lane & 7, lg = lane >> 3;
    const int er = lane >> 2, ec = (lane & 3) * 2;

    // score-MMA ldmatrix address components (stride PADQ)
    const int arow = qrow0 + lr + (lg & 1) * 8;
    const int acol = (lg >> 1) * 8;
    const int brow = kcol0 + lr + (lg >> 1) * 8;
    const int bcol = (lg & 1) * 8;

    const uint32_t uQH = smem_to_u32(sQH), uQL = smem_to_u32(sQL);
    const uint32_t uKH = smem_to_u32(sKH), uKL = smem_to_u32(sKL);
    const uint32_t uVH = smem_to_u32(sVH), uVL = smem_to_u32(sVL);
    const uint32_t uAT = smem_to_u32(sAT);

    // ============================ PASS 1: max & sum ============================
    for (int c = 0; c < NCHUNK; c++) {
        __syncthreads();
        for (int i = tid; i < 1024; i += 256) {
            int r = i >> 3, cc = (i & 7) * 8;
            *(uint4*)(sKH + r * PADQ + cc) = *(const uint4*)(khp + (size_t)(c * 128 + r) * 64 + cc);
            *(uint4*)(sKL + r * PADQ + cc) = *(const uint4*)(klp + (size_t)(c * 128 + r) * 64 + cc);
        }
        __syncthreads();

        float acc[2][8][4];
        #pragma unroll
        for (int i = 0; i < 2; i++)
            #pragma unroll
            for (int j = 0; j < 8; j++)
                #pragma unroll
                for (int l = 0; l < 4; l++) acc[i][j][l] = 0.0f;

        #pragma unroll
        for (int sp = 0; sp < 3; sp++) {
            const uint32_t uA = (sp < 2) ? uQH : uQL;
            const uint32_t uB = (sp == 1) ? uKL : uKH;
            #pragma unroll
            for (int ks = 0; ks < 4; ks++) {
                uint32_t a[2][4];
                #pragma unroll
                for (int mt = 0; mt < 2; mt++)
                    LDSM_X4(a[mt][0], a[mt][1], a[mt][2], a[mt][3],
                            uA + (uint32_t)(((arow + mt * 16) * PADQ + acol + ks * 16) * 2));
                uint32_t bb[4][4];
                #pragma unroll
                for (int nbp = 0; nbp < 4; nbp++)
                    LDSM_X4(bb[nbp][0], bb[nbp][1], bb[nbp][2], bb[nbp][3],
                            uB + (uint32_t)(((brow + nbp * 16) * PADQ + bcol + ks * 16) * 2));
                #pragma unroll
                for (int mt = 0; mt < 2; mt++)
                    #pragma unroll
                    for (int nb = 0; nb < 8; nb++)
                        MMA16816(acc[mt][nb], a[mt][0], a[mt][1], a[mt][2], a[mt][3],
                                 bb[nb >> 1][(nb & 1) * 2], bb[nb >> 1][(nb & 1) * 2 + 1]);
            }
        }

        // per-row chunk max (rows: qrow0 + mt*16 + er, +8)
        float rmx[2][2];
        #pragma unroll
        for (int mt = 0; mt < 2; mt++) {
            float m0 = -1e30f, m1 = -1e30f;
            #pragma unroll
            for (int nb = 0; nb < 8; nb++) {
                m0 = fmaxf(m0, fmaxf(acc[mt][nb][0], acc[mt][nb][1]));
                m1 = fmaxf(m1, fmaxf(acc[mt][nb][2], acc[mt][nb][3]));
            }
            m0 = fmaxf(m0, __shfl_xor_sync(0xffffffffu, m0, 1));
            m0 = fmaxf(m0, __shfl_xor_sync(0xffffffffu, m0, 2));
            m1 = fmaxf(m1, __shfl_xor_sync(0xffffffffu, m1, 1));
            m1 = fmaxf(m1, __shfl_xor_sync(0xffffffffu, m1, 2));
            rmx[mt][0] = m0; rmx[mt][1] = m1;
        }
        float* sP = (w & 1) ? sP1 : sP0;
        if ((lane & 3) == 0) {
            sP[qrow0 + er]      = rmx[0][0];
            sP[qrow0 + er + 8]  = rmx[0][1];
            sP[qrow0 + er + 16] = rmx[1][0];
            sP[qrow0 + er + 24] = rmx[1][1];
        }
        __syncthreads();
        if (tid < 128) {
            float mo = sM[tid];
            float mn = fmaxf(mo, fmaxf(sP0[tid], sP1[tid]));
            sL[tid] *= __expf(mo - mn);
            sM[tid] = mn;
        }
        __syncthreads();

        // per-row sum of exp(s - m_new)
        float mrow[2][2];
        #pragma unroll
        for (int mt = 0; mt < 2; mt++) {
            mrow[mt][0] = sM[qrow0 + mt * 16 + er];
            mrow[mt][1] = sM[qrow0 + mt * 16 + er + 8];
        }
        #pragma unroll
        for (int mt = 0; mt < 2; mt++) {
            float s0 = 0.0f, s1 = 0.0f;
            #pragma unroll
            for (int nb = 0; nb < 8; nb++) {
                s0 += __expf(acc[mt][nb][0] - mrow[mt][0]) + __expf(acc[mt][nb][1] - mrow[mt][0]);
                s1 += __expf(acc[mt][nb][2] - mrow[mt][1]) + __expf(acc[mt][nb][3] - mrow[mt][1]);
            }
            s0 += __shfl_xor_sync(0xffffffffu, s0, 1);
            s0 += __shfl_xor_sync(0xffffffffu, s0, 2);
            s1 += __shfl_xor_sync(0xffffffffu, s1, 1);
            s1 += __shfl_xor_sync(0xffffffffu, s1, 2);
            rmx[mt][0] = s0; rmx[mt][1] = s1;
        }
        if ((lane & 3) == 0) {
            sP[qrow0 + er]      = rmx[0][0];
            sP[qrow0 + er + 8]  = rmx[0][1];
            sP[qrow0 + er + 16] = rmx[1][0];
            sP[qrow0 + er + 24] = rmx[1][1];
        }
        __syncthreads();
        if (tid < 128) sL[tid] += sP0[tid] + sP1[tid];
    }
    __syncthreads();
    if (tid < 128) sInv[tid] = 1.0f / sL[tid];

    // ============================ PASS 2: attn + PV ============================
    // PV role: warp tile 32q x 32e
    const int ecol0 = (w & 1) * 32;
    const int parow = qrow0 + lr + (lg & 1) * 8;       // A rows (attn), stride PADV
    const int pacol = (lg >> 1) * 8;
    const int pbrow = ecol0 + lr + (lg >> 1) * 8;      // B rows (V, e index), stride PADV
    const int pbcol = (lg & 1) * 8;

    float oacc[2][4][4];
    #pragma unroll
    for (int i = 0; i < 2; i++)
        #pragma unroll
        for (int j = 0; j < 4; j++)
            #pragma unroll
            for (int l = 0; l < 4; l++) oacc[i][j][l] = 0.0f;

    const float c09 = 1.0f / 0.9f;

    for (int c = 0; c < NCHUNK; c++) {
        __syncthreads();
        for (int i = tid; i < 1024; i += 256) {
            int r = i >> 3, cc = (i & 7) * 8;
            *(uint4*)(sKH + r * PADQ + cc) = *(const uint4*)(khp + (size_t)(c * 128 + r) * 64 + cc);
            *(uint4*)(sKL + r * PADQ + cc) = *(const uint4*)(klp + (size_t)(c * 128 + r) * 64 + cc);
        }
        for (int i = tid; i < 1024; i += 256) {
            int r = i >> 4, cc = (i & 15) * 8;
            *(uint4*)(sVH + r * PADV + cc) = *(const uint4*)(vhp + (size_t)r * S + c * 128 + cc);
            *(uint4*)(sVL + r * PADV + cc) = *(const uint4*)(vlp + (size_t)r * S + c * 128 + cc);
        }
        __syncthreads();

        float acc[2][8][4];
        #pragma unroll
        for (int i = 0; i < 2; i++)
            #pragma unroll
            for (int j = 0; j < 8; j++)
                #pragma unroll
                for (int l = 0; l < 4; l++) acc[i][j][l] = 0.0f;

        #pragma unroll
        for (int sp = 0; sp < 3; sp++) {
            const uint32_t uA = (sp < 2) ? uQH : uQL;
            const uint32_t uB = (sp == 1) ? uKL : uKH;
            #pragma unroll
            for (int ks = 0; ks < 4; ks++) {
                uint32_t a[2][4];
                #pragma unroll
                for (int mt = 0; mt < 2; mt++)
                    LDSM_X4(a[mt][0], a[mt][1], a[mt][2], a[mt][3],
                            uA + (uint32_t)(((arow + mt * 16) * PADQ + acol + ks * 16) * 2));
                uint32_t bb[4][4];
                #pragma unroll
                for (int nbp = 0; nbp < 4; nbp++)
                    LDSM_X4(bb[nbp][0], bb[nbp][1], bb[nbp][2], bb[nbp][3],
                            uB + (uint32_t)(((brow + nbp * 16) * PADQ + bcol + ks * 16) * 2));
                #pragma unroll
                for (int mt = 0; mt < 2; mt++)
                    #pragma unroll
                    for (int nb = 0; nb < 8; nb++)
                        MMA16816(acc[mt][nb], a[mt][0], a[mt][1], a[mt][2], a[mt][3],
                                 bb[nb >> 1][(nb & 1) * 2], bb[nb >> 1][(nb & 1) * 2 + 1]);
            }
        }

        // normalize + dropout + fp16 -> sAT
        float mrow[2][2], irow[2][2];
        #pragma unroll
        for (int mt = 0; mt < 2; mt++) {
            mrow[mt][0] = sM[qrow0 + mt * 16 + er];
            mrow[mt][1] = sM[qrow0 + mt * 16 + er + 8];
            irow[mt][0] = sInv[qrow0 + mt * 16 + er];
            irow[mt][1] = sInv[qrow0 + mt * 16 + er + 8];
        }
        #pragma unroll
        for (int mt = 0; mt < 2; mt++) {
            const uint32_t qg0 = (uint32_t)((bh * S + q0 + qrow0 + mt * 16 + er) * S);
            const uint32_t qg1 = qg0 + 8u * (uint32_t)S;
            #pragma unroll
            for (int nb = 0; nb < 8; nb++) {
                const uint32_t kg = (uint32_t)(c * 128 + kcol0 + nb * 8 + ec);
                float t0 = __expf(acc[mt][nb][0] - mrow[mt][0]) * irow[mt][0];
                float t1 = __expf(acc[mt][nb][1] - mrow[mt][0]) * irow[mt][0];
                float t2 = __expf(acc[mt][nb][2] - mrow[mt][1]) * irow[mt][1];
                float t3 = __expf(acc[mt][nb][3] - mrow[mt][1]) * irow[mt][1];
                uint32_t b0 = threefry_mask_bits(qg0 + kg);
                uint32_t b1 = threefry_mask_bits(qg0 + kg + 1u);
                uint32_t b2 = threefry_mask_bits(qg1 + kg);
                uint32_t b3 = threefry_mask_bits(qg1 + kg + 1u);
                t0 = (b0 < KEEP_THRESH) ? t0 * c09 : 0.0f;
                t1 = (b1 < KEEP_THRESH) ? t1 * c09 : 0.0f;
                t2 = (b2 < KEEP_THRESH) ? t2 * c09 : 0.0f;
                t3 = (b3 < KEEP_THRESH) ? t3 * c09 : 0.0f;
                uint32_t p0 = (uint32_t)__half_as_ushort(__float2half_rn(t0)) |
                              ((uint32_t)__half_as_ushort(__float2half_rn(t1)) << 16);
                uint32_t p1 = (uint32_t)__half_as_ushort(__float2half_rn(t2)) |
                              ((uint32_t)__half_as_ushort(__float2half_rn(t3)) << 16);
                const int col = kcol0 + nb * 8 + ec;
                *(uint32_t*)(sAT + (qrow0 + mt * 16 + er) * PADV + col) = p0;
                *(uint32_t*)(sAT + (qrow0 + mt * 16 + er + 8) * PADV + col) = p1;
            }
        }
        __syncthreads();

        // PV: oacc += attn(128x128) @ V(128k x 32e per warp)
        #pragma unroll
        for (int ks = 0; ks < 8; ks++) {
            uint32_t a[2][4];
            #pragma unroll
            for (int mt = 0; mt < 2; mt++)
                LDSM_X4(a[mt][0], a[mt][1], a[mt][2], a[mt][3],
                        uAT + (uint32_t)(((parow + mt * 16) * PADV + pacol + ks * 16) * 2));
            uint32_t bh2[2][4], bl2[2][4];
            #pragma unroll
            for (int nbp = 0; nbp < 2; nbp++) {
                LDSM_X4(bh2[nbp][0], bh2[nbp][1], bh2[nbp][2], bh2[nbp][3],
                        uVH + (uint32_t)(((pbrow + nbp * 16) * PADV + pbcol + ks * 16) * 2));
                LDSM_X4(bl2[nbp][0], bl2[nbp][1], bl2[nbp][2], bl2[nbp][3],
                        uVL + (uint32_t)(((pbrow + nbp * 16) * PADV + pbcol + ks * 16) * 2));
            }
            #pragma unroll
            for (int mt = 0; mt < 2; mt++)
                #pragma unroll
                for (int nb = 0; nb < 4; nb++) {
                    MMA16816(oacc[mt][nb], a[mt][0], a[mt][1], a[mt][2], a[mt][3],
                             bh2[nb >> 1][(nb & 1) * 2], bh2[nb >> 1][(nb & 1) * 2 + 1]);
                    MMA16816(oacc[mt][nb], a[mt][0], a[mt][1], a[mt][2], a[mt][3],
                             bl2[nb >> 1][(nb & 1) * 2], bl2[nb >> 1][(nb & 1) * 2 + 1]);
                }
        }
    }

    // epilogue: out[bh][q][e]
    float* dst = out + ((size_t)bh * S + q0 + qrow0) * 64 + ecol0;
    #pragma unroll
    for (int mt = 0; mt < 2; mt++)
        #pragma unroll
        for (int nb = 0; nb < 4; nb++) {
            *(float2*)(dst + (size_t)(mt * 16 + er) * 64 + nb * 8 + ec) =
                make_float2(oacc[mt][nb][0], oacc[mt][nb][1]);
            *(float2*)(dst + (size_t)(mt * 16 + er + 8) * 64 + nb * 8 + ec) =
                make_float2(oacc[mt][nb][2], oacc[mt][nb][3]);
        }
}

// ---------------------------------------------------------------------------
extern "C" void kernel_launch(void* const* d_in, const int* in_sizes, int n_in,
                              void* d_out, int out_size) {
    (void)in_sizes; (void)n_in; (void)out_size;
    const float* query = (const float*)d_in[0];
    const float* key   = (const float*)d_in[1];
    const float* value = (const float*)d_in[2];
    const float* Wq    = (const float*)d_in[3];
    const float* bq    = (const float*)d_in[4];
    const float* Wk    = (const float*)d_in[5];
    const float* bk    = (const float*)d_in[6];
    const float* Wv    = (const float*)d_in[7];
    const float* bv    = (const float*)d_in[8];
    float* out = (float*)d_out;

    const int fl_smem = (4 * 128 * PADQ + 2 * 64 * PADV + 128 * PADV) * 2 + 5 * 128 * 4;

    cudaFuncSetAttribute(flash_kernel, cudaFuncAttributeMaxDynamicSharedMemorySize, fl_smem);

    dim3 pg((B * S * H) / PROJ_TOK, 3);
    proj_kernel<<<pg, 256>>>(query, key, value, Wq, bq, Wk, bk, Wv, bv);

    dim3 fg(S / 128, BH);
    flash_kernel<<<fg, 256, fl_smem>>>(out);
}

// round 5
// speedup vs baseline: 1.2457x; 1.2457x over previous
#include <cuda_runtime.h>
#include <cuda_fp16.h>
#include <stdint.h>

#define B 4
#define S 2048
#define H 8
#define E 64
#define BH (B*H)
#define PADQ 72    // Q/K smem row stride (halves)
#define PADV 136   // V/attn smem row stride (halves)

// ---------------------------------------------------------------------------
// Device scratch (allocation-free)
// ---------------------------------------------------------------------------
__device__ __half g_qh[(size_t)BH*S*E];   // fp16 hi of 0.125*Qproj [bh][s][e]
__device__ __half g_ql[(size_t)BH*S*E];
__device__ __half g_kh[(size_t)BH*S*E];   // [bh][s][e]
__device__ __half g_kl[(size_t)BH*S*E];
__device__ __half g_vh[(size_t)BH*E*S];   // transposed [bh][e][s]
__device__ __half g_vl[(size_t)BH*E*S];
__device__ float  g_sc[(size_t)BH*S*S];   // raw fp32 scores [bh][q][k]
__device__ float  g_pm[(size_t)BH*16*16*128];  // per-tile row max   [bh][qt][kc][r]
__device__ float  g_pl[(size_t)BH*16*16*128];  // per-tile partial l [bh][qt][kc][r]

// ---------------------------------------------------------------------------
// MMA helpers (baseline PTX, works at .target sm_103)
// ---------------------------------------------------------------------------
__device__ __forceinline__ uint32_t smem_to_u32(const void* p) {
    uint32_t a;
    asm("{ .reg .u64 t; cvta.to.shared.u64 t, %1; cvt.u32.u64 %0, t; }" : "=r"(a) : "l"(p));
    return a;
}
#define LDSM_X4(R0, R1, R2, R3, ADDR) \
    asm volatile("ldmatrix.sync.aligned.m8n8.x4.shared.b16 {%0,%1,%2,%3}, [%4];" \
                 : "=r"(R0), "=r"(R1), "=r"(R2), "=r"(R3) : "r"(ADDR))
#define MMA16816(C, A0, A1, A2, A3, B0, B1) \
    asm volatile("mma.sync.aligned.m16n8k16.row.col.f32.f16.f16.f32 " \
                 "{%0,%1,%2,%3}, {%4,%5,%6,%7}, {%8,%9}, {%0,%1,%2,%3};" \
                 : "+f"((C)[0]), "+f"((C)[1]), "+f"((C)[2]), "+f"((C)[3]) \
                 : "r"(A0), "r"(A1), "r"(A2), "r"(A3), "r"(B0), "r"(B1))

// ---------------------------------------------------------------------------
// Threefry2x32 (JAX partitionable) — validated rounds 1/3/4
// ---------------------------------------------------------------------------
__device__ __forceinline__ uint32_t rotl32(uint32_t v, int s) { return __funnelshift_l(v, v, s); }
__device__ __forceinline__ uint32_t threefry_mask_bits(uint32_t idx) {
    const uint32_t ks0 = 0u, ks1 = 42u, ks2 = 0x1BD11BDAu ^ 42u;
    uint32_t x0 = ks0, x1 = idx + ks1;
#define TFR(r) { x0 += x1; x1 = rotl32(x1, r); x1 ^= x0; }
    TFR(13) TFR(15) TFR(26) TFR(6)
    x0 += ks1; x1 += ks2 + 1u;
    TFR(17) TFR(29) TFR(16) TFR(24)
    x0 += ks2; x1 += ks0 + 2u;
    TFR(13) TFR(15) TFR(26) TFR(6)
    x0 += ks0; x1 += ks1 + 3u;
    TFR(17) TFR(29) TFR(16) TFR(24)
    x0 += ks1; x1 += ks2 + 4u;
    TFR(13) TFR(15) TFR(26) TFR(6)
    x0 += ks2; x1 += ks0 + 5u;
#undef TFR
    return x0 ^ x1;
}
#define KEEP_THRESH (7549747u << 9)

// ---------------------------------------------------------------------------
// Kernel 1: QKV projection -> fp16 hi/lo (Q scaled 0.125, V transposed)
// ---------------------------------------------------------------------------
#define PROJ_TOK 32

__global__ __launch_bounds__(256) void proj_kernel(
    const float* __restrict__ qin, const float* __restrict__ kin, const float* __restrict__ vin,
    const float* __restrict__ Wq, const float* __restrict__ bq,
    const float* __restrict__ Wk, const float* __restrict__ bk,
    const float* __restrict__ Wv, const float* __restrict__ bv)
{
    __shared__ float sW[64][68];
    __shared__ float sb[64];
    __shared__ float sx[PROJ_TOK][64];

    const int m = blockIdx.y;
    const float* __restrict__ xin  = (m == 0) ? qin : ((m == 1) ? kin : vin);
    const float* __restrict__ W    = (m == 0) ? Wq  : ((m == 1) ? Wk  : Wv);
    const float* __restrict__ bias = (m == 0) ? bq  : ((m == 1) ? bk  : bv);

    const int tid = threadIdx.x;
    const size_t tok0 = (size_t)blockIdx.x * PROJ_TOK;

    for (int i = tid; i < 64 * 16; i += 256) {
        int r = i >> 4, c = i & 15;
        ((float4*)(&sW[r][0]))[c] = ((const float4*)W)[i];
    }
    if (tid < 64) sb[tid] = bias[tid];
    for (int i = tid; i < PROJ_TOK * 16; i += 256)
        ((float4*)(&sx[0][0]))[i] = ((const float4*)(xin + tok0 * 64))[i];
    __syncthreads();

    const int f  = tid & 63;
    const int tg = tid >> 6;

    float4 wr[16];
    #pragma unroll
    for (int e4 = 0; e4 < 16; e4++) wr[e4] = ((float4*)(&sW[f][0]))[e4];
    const float bsv = sb[f];

    for (int tt = 0; tt < PROJ_TOK; tt += 4) {
        const int t = tt + tg;
        float acc = bsv;
        #pragma unroll
        for (int e4 = 0; e4 < 16; e4++) {
            float4 xv = ((float4*)(&sx[t][0]))[e4];
            acc += xv.x * wr[e4].x + xv.y * wr[e4].y + xv.z * wr[e4].z + xv.w * wr[e4].w;
        }
        const size_t tok = tok0 + t;
        const int b   = (int)(tok >> 14);
        const int rem = (int)(tok & 16383);
        const int s   = rem >> 3;
        const int hh  = rem & 7;
        const size_t bh = (size_t)(b * H + hh);

        float a = (m == 0) ? acc * 0.125f : acc;
        __half hi = __float2half_rn(a);
        __half lo = __float2half_rn(a - __half2float(hi));
        if (m == 0) {
            size_t o = (bh * S + s) * 64 + f;
            g_qh[o] = hi; g_ql[o] = lo;
        } else if (m == 1) {
            size_t o = (bh * S + s) * 64 + f;
            g_kh[o] = hi; g_kl[o] = lo;
        } else {
            size_t o = (bh * 64 + f) * S + s;
            g_vh[o] = hi; g_vl[o] = lo;
        }
    }
}

// ---------------------------------------------------------------------------
// Kernel 2: scores + per-tile stats.
// CTA: 128q x 128k; 8 warps = 4(q) x 2(k); warp tile 32q x 64k.
// Writes raw fp32 scores [bh][q][k] + per-tile (m_t, l_t).
// ---------------------------------------------------------------------------
__global__ __launch_bounds__(256, 2) void scores_kernel()
{
    extern __shared__ char smraw[];
    __half* sQH = (__half*)smraw;            // [128][PADQ]
    __half* sQL = sQH + 128 * PADQ;
    __half* sKH = sQL + 128 * PADQ;
    __half* sKL = sKH + 128 * PADQ;
    float*  sP0 = (float*)(sKL + 128 * PADQ); // [128]
    float*  sP1 = sP0 + 128;                  // [128]
    float*  sMr = sP1 + 128;                  // [128] tile row max

    const int tid = threadIdx.x;
    const int kc = blockIdx.x, qt = blockIdx.y, bh = blockIdx.z;
    const int k0 = kc * 128, q0 = qt * 128;

    const __half* qhp = g_qh + ((size_t)bh * S + q0) * 64;
    const __half* qlp = g_ql + ((size_t)bh * S + q0) * 64;
    const __half* khp = g_kh + ((size_t)bh * S + k0) * 64;
    const __half* klp = g_kl + ((size_t)bh * S + k0) * 64;

    for (int i = tid; i < 1024; i += 256) {
        int r = i >> 3, c = (i & 7) * 8;
        *(uint4*)(sQH + r * PADQ + c) = *(const uint4*)(qhp + r * 64 + c);
        *(uint4*)(sQL + r * PADQ + c) = *(const uint4*)(qlp + r * 64 + c);
        *(uint4*)(sKH + r * PADQ + c) = *(const uint4*)(khp + r * 64 + c);
        *(uint4*)(sKL + r * PADQ + c) = *(const uint4*)(klp + r * 64 + c);
    }
    __syncthreads();

    const int w = tid >> 5, lane = tid & 31;
    const int qrow0 = (w >> 1) * 32, kcol0 = (w & 1) * 64;
    const int lr = lane & 7, lg = lane >> 3;
    const int er = lane >> 2, ec = (lane & 3) * 2;

    const int arow = qrow0 + lr + (lg & 1) * 8;
    const int acol = (lg >> 1) * 8;
    const int brow = kcol0 + lr + (lg >> 1) * 8;
    const int bcol = (lg & 1) * 8;

    const uint32_t uQH = smem_to_u32(sQH), uQL = smem_to_u32(sQL);
    const uint32_t uKH = smem_to_u32(sKH), uKL = smem_to_u32(sKL);

    float acc[2][8][4];
    #pragma unroll
    for (int i = 0; i < 2; i++)
        #pragma unroll
        for (int j = 0; j < 8; j++)
            #pragma unroll
            for (int l = 0; l < 4; l++) acc[i][j][l] = 0.0f;

    #pragma unroll
    for (int sp = 0; sp < 3; sp++) {
        const uint32_t uA = (sp < 2) ? uQH : uQL;
        const uint32_t uB = (sp == 1) ? uKL : uKH;
        #pragma unroll
        for (int ks = 0; ks < 4; ks++) {
            uint32_t a[2][4];
            #pragma unroll
            for (int mt = 0; mt < 2; mt++)
                LDSM_X4(a[mt][0], a[mt][1], a[mt][2], a[mt][3],
                        uA + (uint32_t)(((arow + mt * 16) * PADQ + acol + ks * 16) * 2));
            uint32_t bb[4][4];
            #pragma unroll
            for (int nbp = 0; nbp < 4; nbp++)
                LDSM_X4(bb[nbp][0], bb[nbp][1], bb[nbp][2], bb[nbp][3],
                        uKH == uB || uKL == uB ?
                        uB + (uint32_t)(((brow + nbp * 16) * PADQ + bcol + ks * 16) * 2) :
                        uB);
            #pragma unroll
            for (int mt = 0; mt < 2; mt++)
                #pragma unroll
                for (int nb = 0; nb < 8; nb++)
                    MMA16816(acc[mt][nb], a[mt][0], a[mt][1], a[mt][2], a[mt][3],
                             bb[nb >> 1][(nb & 1) * 2], bb[nb >> 1][(nb & 1) * 2 + 1]);
        }
    }

    // ---- per-tile row max ----
    float rr[2][2];
    #pragma unroll
    for (int mt = 0; mt < 2; mt++) {
        float m0 = -1e30f, m1 = -1e30f;
        #pragma unroll
        for (int nb = 0; nb < 8; nb++) {
            m0 = fmaxf(m0, fmaxf(acc[mt][nb][0], acc[mt][nb][1]));
            m1 = fmaxf(m1, fmaxf(acc[mt][nb][2], acc[mt][nb][3]));
        }
        m0 = fmaxf(m0, __shfl_xor_sync(0xffffffffu, m0, 1));
        m0 = fmaxf(m0, __shfl_xor_sync(0xffffffffu, m0, 2));
        m1 = fmaxf(m1, __shfl_xor_sync(0xffffffffu, m1, 1));
        m1 = fmaxf(m1, __shfl_xor_sync(0xffffffffu, m1, 2));
        rr[mt][0] = m0; rr[mt][1] = m1;
    }
    float* sP = (w & 1) ? sP1 : sP0;
    if ((lane & 3) == 0) {
        sP[qrow0 + er]      = rr[0][0];
        sP[qrow0 + er + 8]  = rr[0][1];
        sP[qrow0 + er + 16] = rr[1][0];
        sP[qrow0 + er + 24] = rr[1][1];
    }
    __syncthreads();
    if (tid < 128) sMr[tid] = fmaxf(sP0[tid], sP1[tid]);
    __syncthreads();

    // ---- per-tile partial l (sum of exp(s - m_t)) ----
    float mrow[2][2];
    #pragma unroll
    for (int mt = 0; mt < 2; mt++) {
        mrow[mt][0] = sMr[qrow0 + mt * 16 + er];
        mrow[mt][1] = sMr[qrow0 + mt * 16 + er + 8];
    }
    #pragma unroll
    for (int mt = 0; mt < 2; mt++) {
        float s0 = 0.0f, s1 = 0.0f;
        #pragma unroll
        for (int nb = 0; nb < 8; nb++) {
            s0 += __expf(acc[mt][nb][0] - mrow[mt][0]) + __expf(acc[mt][nb][1] - mrow[mt][0]);
            s1 += __expf(acc[mt][nb][2] - mrow[mt][1]) + __expf(acc[mt][nb][3] - mrow[mt][1]);
        }
        s0 += __shfl_xor_sync(0xffffffffu, s0, 1);
        s0 += __shfl_xor_sync(0xffffffffu, s0, 2);
        s1 += __shfl_xor_sync(0xffffffffu, s1, 1);
        s1 += __shfl_xor_sync(0xffffffffu, s1, 2);
        rr[mt][0] = s0; rr[mt][1] = s1;
    }
    if ((lane & 3) == 0) {
        sP[qrow0 + er]      = rr[0][0];
        sP[qrow0 + er + 8]  = rr[0][1];
        sP[qrow0 + er + 16] = rr[1][0];
        sP[qrow0 + er + 24] = rr[1][1];
    }
    __syncthreads();
    if (tid < 128) {
        const size_t pidx = (((size_t)bh * 16 + qt) * 16 + kc) * 128 + tid;
        g_pm[pidx] = sMr[tid];
        g_pl[pidx] = sP0[tid] + sP1[tid];
    }

    // ---- raw scores to gmem ----
    float* dst = g_sc + ((size_t)bh * S + q0 + qrow0) * S + k0 + kcol0;
    #pragma unroll
    for (int mt = 0; mt < 2; mt++)
        #pragma unroll
        for (int nb = 0; nb < 8; nb++) {
            *(float2*)(dst + (size_t)(mt * 16 + er) * S + nb * 8 + ec) =
                make_float2(acc[mt][nb][0], acc[mt][nb][1]);
            *(float2*)(dst + (size_t)(mt * 16 + er + 8) * S + nb * 8 + ec) =
                make_float2(acc[mt][nb][2], acc[mt][nb][3]);
        }
}

// ---------------------------------------------------------------------------
// Kernel 3: fused softmax + dropout + fp16 + PV.
// CTA: 128q x one bh; 8 warps.  Softmax role: 4(q)x2(k); PV role: 4(q)x2(e).
// ---------------------------------------------------------------------------
__global__ __launch_bounds__(256, 2) void pv_kernel(float* __restrict__ out)
{
    extern __shared__ char smraw[];
    __half* sVH = (__half*)smraw;            // [64][PADV]
    __half* sVL = sVH + 64 * PADV;
    __half* sAT = sVL + 64 * PADV;           // [128][PADV]
    float*  sM  = (float*)(sAT + 128 * PADV);// [128]
    float*  sInv = sM + 128;                 // [128]

    const int tid = threadIdx.x;
    const int qt = blockIdx.x, bh = blockIdx.y;
    const int q0 = qt * 128;

    // combine per-tile stats -> m, 1/l
    if (tid < 128) {
        const size_t pbase = (((size_t)bh * 16 + qt) * 16) * 128 + tid;
        float m = -1e30f;
        float pm[16];
        #pragma unroll
        for (int t = 0; t < 16; t++) { pm[t] = g_pm[pbase + t * 128]; m = fmaxf(m, pm[t]); }
        float l = 0.0f;
        #pragma unroll
        for (int t = 0; t < 16; t++) l += g_pl[pbase + t * 128] * __expf(pm[t] - m);
        sM[tid] = m;
        sInv[tid] = 1.0f / l;
    }
    __syncthreads();

    const int w = tid >> 5, lane = tid & 31;
    const int qrow0 = (w >> 1) * 32, kcol0 = (w & 1) * 64;
    const int lr = lane & 7, lg = lane >> 3;
    const int er = lane >> 2, ec = (lane & 3) * 2;

    // PV ldmatrix addressing (stride PADV)
    const int ecol0 = (w & 1) * 32;
    const int parow = qrow0 + lr + (lg & 1) * 8;
    const int pacol = (lg >> 1) * 8;
    const int pbrow = ecol0 + lr + (lg >> 1) * 8;
    const int pbcol = (lg & 1) * 8;

    const uint32_t uVH = smem_to_u32(sVH), uVL = smem_to_u32(sVL);
    const uint32_t uAT = smem_to_u32(sAT);

    const __half* vhp = g_vh + (size_t)bh * 64 * S;
    const __half* vlp = g_vl + (size_t)bh * 64 * S;

    // cached per-thread stats (4 rows)
    const float m0 = sM[qrow0 + er],        i0 = sInv[qrow0 + er];
    const float m1 = sM[qrow0 + er + 8],    i1 = sInv[qrow0 + er + 8];
    const float m2 = sM[qrow0 + 16 + er],   i2 = sInv[qrow0 + 16 + er];
    const float m3 = sM[qrow0 + 16 + er + 8], i3 = sInv[qrow0 + 16 + er + 8];

    // score row pointers (4 rows per thread)
    const float* sr0 = g_sc + ((size_t)bh * S + q0 + qrow0 + er) * S;
    const float* sr1 = sr0 + (size_t)8 * S;
    const float* sr2 = sr0 + (size_t)16 * S;
    const float* sr3 = sr0 + (size_t)24 * S;

    const uint32_t qg0 = (uint32_t)((bh * S + q0 + qrow0 + er) * S);
    const uint32_t qg1 = qg0 + 8u * (uint32_t)S;
    const uint32_t qg2 = qg0 + 16u * (uint32_t)S;
    const uint32_t qg3 = qg0 + 24u * (uint32_t)S;

    float oacc[2][4][4];
    #pragma unroll
    for (int i = 0; i < 2; i++)
        #pragma unroll
        for (int j = 0; j < 4; j++)
            #pragma unroll
            for (int l = 0; l < 4; l++) oacc[i][j][l] = 0.0f;

    const float c09 = 1.0f / 0.9f;

    for (int c = 0; c < 16; c++) {
        // V chunk -> smem
        for (int i = tid; i < 1024; i += 256) {
            int r = i >> 4, cc = (i & 15) * 8;
            *(uint4*)(sVH + r * PADV + cc) = *(const uint4*)(vhp + (size_t)r * S + c * 128 + cc);
            *(uint4*)(sVL + r * PADV + cc) = *(const uint4*)(vlp + (size_t)r * S + c * 128 + cc);
        }

        // scores -> attn fp16 -> sAT (this thread's 4 rows x 16 cols)
        #pragma unroll
        for (int nb = 0; nb < 8; nb++) {
            const int col = c * 128 + kcol0 + nb * 8 + ec;
            float2 v0 = *(const float2*)(sr0 + col);
            float2 v1 = *(const float2*)(sr1 + col);
            float2 v2 = *(const float2*)(sr2 + col);
            float2 v3 = *(const float2*)(sr3 + col);

            float t0a = __expf(v0.x - m0) * i0, t0b = __expf(v0.y - m0) * i0;
            float t1a = __expf(v1.x - m1) * i1, t1b = __expf(v1.y - m1) * i1;
            float t2a = __expf(v2.x - m2) * i2, t2b = __expf(v2.y - m2) * i2;
            float t3a = __expf(v3.x - m3) * i3, t3b = __expf(v3.y - m3) * i3;

            const uint32_t kg = (uint32_t)col;
            uint32_t b0a = threefry_mask_bits(qg0 + kg), b0b = threefry_mask_bits(qg0 + kg + 1u);
            uint32_t b1a = threefry_mask_bits(qg1 + kg), b1b = threefry_mask_bits(qg1 + kg + 1u);
            uint32_t b2a = threefry_mask_bits(qg2 + kg), b2b = threefry_mask_bits(qg2 + kg + 1u);
            uint32_t b3a = threefry_mask_bits(qg3 + kg), b3b = threefry_mask_bits(qg3 + kg + 1u);

            t0a = (b0a < KEEP_THRESH) ? t0a * c09 : 0.0f;
            t0b = (b0b < KEEP_THRESH) ? t0b * c09 : 0.0f;
            t1a = (b1a < KEEP_THRESH) ? t1a * c09 : 0.0f;
            t1b = (b1b < KEEP_THRESH) ? t1b * c09 : 0.0f;
            t2a = (b2a < KEEP_THRESH) ? t2a * c09 : 0.0f;
            t2b = (b2b < KEEP_THRESH) ? t2b * c09 : 0.0f;
            t3a = (b3a < KEEP_THRESH) ? t3a * c09 : 0.0f;
            t3b = (b3b < KEEP_THRESH) ? t3b * c09 : 0.0f;

            const int scol = kcol0 + nb * 8 + ec;
            *(uint32_t*)(sAT + (qrow0 + er) * PADV + scol) =
                (uint32_t)__half_as_ushort(__float2half_rn(t0a)) |
                ((uint32_t)__half_as_ushort(__float2half_rn(t0b)) << 16);
            *(uint32_t*)(sAT + (qrow0 + er + 8) * PADV + scol) =
                (uint32_t)__half_as_ushort(__float2half_rn(t1a)) |
                ((uint32_t)__half_as_ushort(__float2half_rn(t1b)) << 16);
            *(uint32_t*)(sAT + (qrow0 + 16 + er) * PADV + scol) =
                (uint32_t)__half_as_ushort(__float2half_rn(t2a)) |
                ((uint32_t)__half_as_ushort(__float2half_rn(t2b)) << 16);
            *(uint32_t*)(sAT + (qrow0 + 16 + er + 8) * PADV + scol) =
                (uint32_t)__half_as_ushort(__float2half_rn(t3a)) |
                ((uint32_t)__half_as_ushort(__float2half_rn(t3b)) << 16);
        }
        __syncthreads();

        // PV MMA
        #pragma unroll
        for (int ks = 0; ks < 8; ks++) {
            uint32_t a[2][4];
            #pragma unroll
            for (int mt = 0; mt < 2; mt++)
                LDSM_X4(a[mt][0], a[mt][1], a[mt][2], a[mt][3],
                        uAT + (uint32_t)(((parow + mt * 16) * PADV + pacol + ks * 16) * 2));
            uint32_t bh2[2][4], bl2[2][4];
            #pragma unroll
            for (int nbp = 0; nbp < 2; nbp++) {
                LDSM_X4(bh2[nbp][0], bh2[nbp][1], bh2[nbp][2], bh2[nbp][3],
                        uVH + (uint32_t)(((pbrow + nbp * 16) * PADV + pbcol + ks * 16) * 2));
                LDSM_X4(bl2[nbp][0], bl2[nbp][1], bl2[nbp][2], bl2[nbp][3],
                        uVL + (uint32_t)(((pbrow + nbp * 16) * PADV + pbcol + ks * 16) * 2));
            }
            #pragma unroll
            for (int mt = 0; mt < 2; mt++)
                #pragma unroll
                for (int nb = 0; nb < 4; nb++) {
                    MMA16816(oacc[mt][nb], a[mt][0], a[mt][1], a[mt][2], a[mt][3],
                             bh2[nb >> 1][(nb & 1) * 2], bh2[nb >> 1][(nb & 1) * 2 + 1]);
                    MMA16816(oacc[mt][nb], a[mt][0], a[mt][1], a[mt][2], a[mt][3],
                             bl2[nb >> 1][(nb & 1) * 2], bl2[nb >> 1][(nb & 1) * 2 + 1]);
                }
        }
        __syncthreads();
    }

    // epilogue
    float* dst = out + ((size_t)bh * S + q0 + qrow0) * 64 + ecol0;
    #pragma unroll
    for (int mt = 0; mt < 2; mt++)
        #pragma unroll
        for (int nb = 0; nb < 4; nb++) {
            *(float2*)(dst + (size_t)(mt * 16 + er) * 64 + nb * 8 + ec) =
                make_float2(oacc[mt][nb][0], oacc[mt][nb][1]);
            *(float2*)(dst + (size_t)(mt * 16 + er + 8) * 64 + nb * 8 + ec) =
                make_float2(oacc[mt][nb][2], oacc[mt][nb][3]);
        }
}

// ---------------------------------------------------------------------------
extern "C" void kernel_launch(void* const* d_in, const int* in_sizes, int n_in,
                              void* d_out, int out_size) {
    (void)in_sizes; (void)n_in; (void)out_size;
    const float* query = (const float*)d_in[0];
    const float* key   = (const float*)d_in[1];
    const float* value = (const float*)d_in[2];
    const float* Wq    = (const float*)d_in[3];
    const float* bq    = (const float*)d_in[4];
    const float* Wk    = (const float*)d_in[5];
    const float* bk    = (const float*)d_in[6];
    const float* Wv    = (const float*)d_in[7];
    const float* bv    = (const float*)d_in[8];
    float* out = (float*)d_out;

    const int sc_smem = 4 * 128 * PADQ * 2 + 3 * 128 * 4;                  // 75264
    const int pv_smem = (2 * 64 * PADV + 128 * PADV) * 2 + 2 * 128 * 4;    // 53248+17408+1024 = 70656

    cudaFuncSetAttribute(scores_kernel, cudaFuncAttributeMaxDynamicSharedMemorySize, sc_smem);
    cudaFuncSetAttribute(pv_kernel,     cudaFuncAttributeMaxDynamicSharedMemorySize, pv_smem);

    dim3 pg((B * S * H) / PROJ_TOK, 3);
    proj_kernel<<<pg, 256>>>(query, key, value, Wq, bq, Wk, bk, Wv, bv);

    dim3 sg(S / 128, S / 128, BH);
    scores_kernel<<<sg, 256, sc_smem>>>();

    dim3 ag(S / 128, BH);
    pv_kernel<<<ag, 256, pv_smem>>>(out);
}

// round 6
// speedup vs baseline: 1.2881x; 1.0340x over previous
#include <cuda_runtime.h>
#include <cuda_fp16.h>
#include <stdint.h>

#define B 4
#define S 2048
#define H 8
#define E 64
#define BH (B*H)
#define PADQ 72    // Q/K smem row stride (halves)
#define PADV 136   // V/attn smem row stride (halves)

// ---------------------------------------------------------------------------
// Device scratch (allocation-free)
// ---------------------------------------------------------------------------
__device__ __half g_qh[(size_t)BH*S*E];   // fp16 hi of 0.125*Qproj [bh][s][e]
__device__ __half g_ql[(size_t)BH*S*E];
__device__ __half g_kh[(size_t)BH*S*E];   // [bh][s][e]
__device__ __half g_kl[(size_t)BH*S*E];
__device__ __half g_vh[(size_t)BH*E*S];   // transposed [bh][e][s]
__device__ __half g_vl[(size_t)BH*E*S];
__device__ float  g_sc[(size_t)BH*S*S];   // raw fp32 scores [bh][q][k]
__device__ float  g_pm[(size_t)BH*16*16*128];  // per-tile row max
__device__ float  g_pl[(size_t)BH*16*16*128];  // per-tile partial l
__device__ uint32_t g_mask[(size_t)BH*S*(S/32)]; // dropout keep-bits [bh][q][k/32]

// ---------------------------------------------------------------------------
// MMA helpers (baseline PTX, works at .target sm_103)
// ---------------------------------------------------------------------------
__device__ __forceinline__ uint32_t smem_to_u32(const void* p) {
    uint32_t a;
    asm("{ .reg .u64 t; cvta.to.shared.u64 t, %1; cvt.u32.u64 %0, t; }" : "=r"(a) : "l"(p));
    return a;
}
#define LDSM_X4(R0, R1, R2, R3, ADDR) \
    asm volatile("ldmatrix.sync.aligned.m8n8.x4.shared.b16 {%0,%1,%2,%3}, [%4];" \
                 : "=r"(R0), "=r"(R1), "=r"(R2), "=r"(R3) : "r"(ADDR))
#define MMA16816(C, A0, A1, A2, A3, B0, B1) \
    asm volatile("mma.sync.aligned.m16n8k16.row.col.f32.f16.f16.f32 " \
                 "{%0,%1,%2,%3}, {%4,%5,%6,%7}, {%8,%9}, {%0,%1,%2,%3};" \
                 : "+f"((C)[0]), "+f"((C)[1]), "+f"((C)[2]), "+f"((C)[3]) \
                 : "r"(A0), "r"(A1), "r"(A2), "r"(A3), "r"(B0), "r"(B1))

// ---------------------------------------------------------------------------
// Threefry2x32 (JAX partitionable) — validated rounds 1/3/4/5
// ---------------------------------------------------------------------------
__device__ __forceinline__ uint32_t rotl32(uint32_t v, int s) { return __funnelshift_l(v, v, s); }
__device__ __forceinline__ uint32_t threefry_mask_bits(uint32_t idx) {
    const uint32_t ks0 = 0u, ks1 = 42u, ks2 = 0x1BD11BDAu ^ 42u;
    uint32_t x0 = ks0, x1 = idx + ks1;
#define TFR(r) { x0 += x1; x1 = rotl32(x1, r); x1 ^= x0; }
    TFR(13) TFR(15) TFR(26) TFR(6)
    x0 += ks1; x1 += ks2 + 1u;
    TFR(17) TFR(29) TFR(16) TFR(24)
    x0 += ks2; x1 += ks0 + 2u;
    TFR(13) TFR(15) TFR(26) TFR(6)
    x0 += ks0; x1 += ks1 + 3u;
    TFR(17) TFR(29) TFR(16) TFR(24)
    x0 += ks1; x1 += ks2 + 4u;
    TFR(13) TFR(15) TFR(26) TFR(6)
    x0 += ks2; x1 += ks0 + 5u;
#undef TFR
    return x0 ^ x1;
}
#define KEEP_THRESH (7549747u << 9)

// ---------------------------------------------------------------------------
// Kernel 1: QKV projection, coalesced.  CTA = 128 s-rows of one (bh, matrix).
// Q/K: [bh][s][e] direct coalesced stores.  V: smem transpose -> [bh][e][s].
// ---------------------------------------------------------------------------
#define SYP 133   // sY stride (uint32), coprime with 32

__global__ __launch_bounds__(256) void proj_kernel(
    const float* __restrict__ qin, const float* __restrict__ kin, const float* __restrict__ vin,
    const float* __restrict__ Wq, const float* __restrict__ bq,
    const float* __restrict__ Wk, const float* __restrict__ bk,
    const float* __restrict__ Wv, const float* __restrict__ bv)
{
    extern __shared__ char dyn[];
    float* sW = (float*)dyn;                 // [64][68]
    float* sbv = sW + 64 * 68;               // [64]
    float* sx = sbv + 64;                    // [128][64]
    uint32_t* sY = (uint32_t*)(sx + 128*64); // [64][SYP]  (V only)

    const int tid = threadIdx.x;
    const int s0 = blockIdx.x * 128;
    const int bh = blockIdx.y;
    const int m  = blockIdx.z;
    const int b = bh >> 3, h = bh & 7;

    const float* __restrict__ xin  = (m == 0) ? qin : ((m == 1) ? kin : vin);
    const float* __restrict__ W    = (m == 0) ? Wq  : ((m == 1) ? Wk  : Wv);
    const float* __restrict__ bias = (m == 0) ? bq  : ((m == 1) ? bk  : bv);

    for (int i = tid; i < 64 * 16; i += 256) {
        int r = i >> 4, c = i & 15;
        ((float4*)(sW + r * 68))[c] = ((const float4*)W)[i];
    }
    if (tid < 64) sbv[tid] = bias[tid];
    for (int i = tid; i < 128 * 16; i += 256) {
        int s = i >> 4, c = i & 15;
        ((float4*)(sx + s * 64))[c] =
            ((const float4*)(xin + ((size_t)((b * S + s0 + s) * H + h)) * 64))[c];
    }
    __syncthreads();

    const int f = tid & 63, sg = tid >> 6;

    float4 wr[16];
    #pragma unroll
    for (int e4 = 0; e4 < 16; e4++) wr[e4] = ((float4*)(sW + f * 68))[e4];
    const float bf = sbv[f];
    const float qs = (m == 0) ? 0.125f : 1.0f;

    if (m < 2) {
        __half* dh = ((m == 0) ? g_qh : g_kh) + ((size_t)bh * S + s0) * 64 + f;
        __half* dl = ((m == 0) ? g_ql : g_kl) + ((size_t)bh * S + s0) * 64 + f;
        #pragma unroll 4
        for (int ss = 0; ss < 32; ss++) {
            const int s = sg * 32 + ss;
            float acc = bf;
            #pragma unroll
            for (int e4 = 0; e4 < 16; e4++) {
                float4 xv = ((float4*)(sx + s * 64))[e4];
                acc += xv.x * wr[e4].x + xv.y * wr[e4].y + xv.z * wr[e4].z + xv.w * wr[e4].w;
            }
            acc *= qs;
            __half hi = __float2half_rn(acc);
            __half lo = __float2half_rn(acc - __half2float(hi));
            dh[(size_t)s * 64] = hi;
            dl[(size_t)s * 64] = lo;
        }
    } else {
        #pragma unroll 4
        for (int ss = 0; ss < 32; ss++) {
            const int s = sg * 32 + ss;
            float acc = bf;
            #pragma unroll
            for (int e4 = 0; e4 < 16; e4++) {
                float4 xv = ((float4*)(sx + s * 64))[e4];
                acc += xv.x * wr[e4].x + xv.y * wr[e4].y + xv.z * wr[e4].z + xv.w * wr[e4].w;
            }
            __half hi = __float2half_rn(acc);
            __half lo = __float2half_rn(acc - __half2float(hi));
            sY[f * SYP + s] = (uint32_t)__half_as_ushort(hi) |
                              ((uint32_t)__half_as_ushort(lo) << 16);
        }
        __syncthreads();
        // transpose write: [e][s], 16B granules
        for (int i = tid; i < 1024; i += 256) {
            const int fr = i >> 4, c = i & 15;
            const int sb8 = c * 8;
            uint32_t y[8];
            #pragma unroll
            for (int j = 0; j < 8; j++) y[j] = sY[fr * SYP + sb8 + j];
            uint4 hv, lv;
            hv.x = (y[0] & 0xffffu) | (y[1] << 16);
            hv.y = (y[2] & 0xffffu) | (y[3] << 16);
            hv.z = (y[4] & 0xffffu) | (y[5] << 16);
            hv.w = (y[6] & 0xffffu) | (y[7] << 16);
            lv.x = (y[0] >> 16) | (y[1] & 0xffff0000u);
            lv.y = (y[2] >> 16) | (y[3] & 0xffff0000u);
            lv.z = (y[4] >> 16) | (y[5] & 0xffff0000u);
            lv.w = (y[6] >> 16) | (y[7] & 0xffff0000u);
            const size_t off = ((size_t)bh * 64 + fr) * S + s0 + sb8;
            *(uint4*)(g_vh + off) = hv;
            *(uint4*)(g_vl + off) = lv;
        }
    }
}
#define PROJ_SMEM ((64*68 + 64 + 128*64) * 4 + 64 * SYP * 4)

// ---------------------------------------------------------------------------
// Kernel 2: scores + per-tile stats + DROPOUT MASK (threefry on idle alu pipe).
// CTA: 128q x 128k; 8 warps = 4(q) x 2(k); warp tile 32q x 64k.
// ---------------------------------------------------------------------------
__global__ __launch_bounds__(256, 2) void scores_kernel()
{
    extern __shared__ char smraw[];
    __half* sQH = (__half*)smraw;            // [128][PADQ]
    __half* sQL = sQH + 128 * PADQ;
    __half* sKH = sQL + 128 * PADQ;
    __half* sKL = sKH + 128 * PADQ;
    float*  sP0 = (float*)(sKL + 128 * PADQ); // [128]
    float*  sP1 = sP0 + 128;
    float*  sMr = sP1 + 128;

    const int tid = threadIdx.x;
    const int kc = blockIdx.x, qt = blockIdx.y, bh = blockIdx.z;
    const int k0 = kc * 128, q0 = qt * 128;

    const __half* qhp = g_qh + ((size_t)bh * S + q0) * 64;
    const __half* qlp = g_ql + ((size_t)bh * S + q0) * 64;
    const __half* khp = g_kh + ((size_t)bh * S + k0) * 64;
    const __half* klp = g_kl + ((size_t)bh * S + k0) * 64;

    for (int i = tid; i < 1024; i += 256) {
        int r = i >> 3, c = (i & 7) * 8;
        *(uint4*)(sQH + r * PADQ + c) = *(const uint4*)(qhp + r * 64 + c);
        *(uint4*)(sQL + r * PADQ + c) = *(const uint4*)(qlp + r * 64 + c);
        *(uint4*)(sKH + r * PADQ + c) = *(const uint4*)(khp + r * 64 + c);
        *(uint4*)(sKL + r * PADQ + c) = *(const uint4*)(klp + r * 64 + c);
    }
    __syncthreads();

    const int w = tid >> 5, lane = tid & 31;
    const int qrow0 = (w >> 1) * 32, kcol0 = (w & 1) * 64;
    const int lr = lane & 7, lg = lane >> 3;
    const int er = lane >> 2, ec = (lane & 3) * 2;

    const int arow = qrow0 + lr + (lg & 1) * 8;
    const int acol = (lg >> 1) * 8;
    const int brow = kcol0 + lr + (lg >> 1) * 8;
    const int bcol = (lg & 1) * 8;

    const uint32_t uQH = smem_to_u32(sQH), uQL = smem_to_u32(sQL);
    const uint32_t uKH = smem_to_u32(sKH), uKL = smem_to_u32(sKL);

    float acc[2][8][4];
    #pragma unroll
    for (int i = 0; i < 2; i++)
        #pragma unroll
        for (int j = 0; j < 8; j++)
            #pragma unroll
            for (int l = 0; l < 4; l++) acc[i][j][l] = 0.0f;

    #pragma unroll
    for (int sp = 0; sp < 3; sp++) {
        const uint32_t uA = (sp < 2) ? uQH : uQL;
        const uint32_t uB = (sp == 1) ? uKL : uKH;
        #pragma unroll
        for (int ks = 0; ks < 4; ks++) {
            uint32_t a[2][4];
            #pragma unroll
            for (int mt = 0; mt < 2; mt++)
                LDSM_X4(a[mt][0], a[mt][1], a[mt][2], a[mt][3],
                        uA + (uint32_t)(((arow + mt * 16) * PADQ + acol + ks * 16) * 2));
            uint32_t bb[4][4];
            #pragma unroll
            for (int nbp = 0; nbp < 4; nbp++)
                LDSM_X4(bb[nbp][0], bb[nbp][1], bb[nbp][2], bb[nbp][3],
                        uB + (uint32_t)(((brow + nbp * 16) * PADQ + bcol + ks * 16) * 2));
            #pragma unroll
            for (int mt = 0; mt < 2; mt++)
                #pragma unroll
                for (int nb = 0; nb < 8; nb++)
                    MMA16816(acc[mt][nb], a[mt][0], a[mt][1], a[mt][2], a[mt][3],
                             bb[nb >> 1][(nb & 1) * 2], bb[nb >> 1][(nb & 1) * 2 + 1]);
        }
    }

    // ---- dropout mask for this tile (4 rows x 16 cols per thread) ----
    {
        const uint32_t kbase = (uint32_t)(k0 + kcol0 + ec);
        #pragma unroll
        for (int rr = 0; rr < 4; rr++) {
            const int qg = q0 + qrow0 + (rr >> 1) * 16 + (rr & 1) * 8 + er;
            const uint32_t idxbase = (uint32_t)(bh * S + qg) * (uint32_t)S + kbase;
            uint32_t w0 = 0, w1 = 0;
            #pragma unroll
            for (int nb = 0; nb < 8; nb++) {
                const uint32_t i0 = idxbase + nb * 8;
                uint32_t bA = (threefry_mask_bits(i0) < KEEP_THRESH) ? 1u : 0u;
                uint32_t bB = (threefry_mask_bits(i0 + 1u) < KEEP_THRESH) ? 2u : 0u;
                const uint32_t put = (bA | bB) << ((nb & 3) * 8 + ec);
                if (nb < 4) w0 |= put; else w1 |= put;
            }
            w0 |= __shfl_xor_sync(0xffffffffu, w0, 1);
            w0 |= __shfl_xor_sync(0xffffffffu, w0, 2);
            w1 |= __shfl_xor_sync(0xffffffffu, w1, 1);
            w1 |= __shfl_xor_sync(0xffffffffu, w1, 2);
            if ((lane & 3) == 0)
                *(uint2*)(g_mask + (size_t)(bh * S + qg) * 64 + kc * 4 + (kcol0 >> 5)) =
                    make_uint2(w0, w1);
        }
    }

    // ---- per-tile row max ----
    float rr2[2][2];
    #pragma unroll
    for (int mt = 0; mt < 2; mt++) {
        float m0 = -1e30f, m1 = -1e30f;
        #pragma unroll
        for (int nb = 0; nb < 8; nb++) {
            m0 = fmaxf(m0, fmaxf(acc[mt][nb][0], acc[mt][nb][1]));
            m1 = fmaxf(m1, fmaxf(acc[mt][nb][2], acc[mt][nb][3]));
        }
        m0 = fmaxf(m0, __shfl_xor_sync(0xffffffffu, m0, 1));
        m0 = fmaxf(m0, __shfl_xor_sync(0xffffffffu, m0, 2));
        m1 = fmaxf(m1, __shfl_xor_sync(0xffffffffu, m1, 1));
        m1 = fmaxf(m1, __shfl_xor_sync(0xffffffffu, m1, 2));
        rr2[mt][0] = m0; rr2[mt][1] = m1;
    }
    float* sP = (w & 1) ? sP1 : sP0;
    if ((lane & 3) == 0) {
        sP[qrow0 + er]      = rr2[0][0];
        sP[qrow0 + er + 8]  = rr2[0][1];
        sP[qrow0 + er + 16] = rr2[1][0];
        sP[qrow0 + er + 24] = rr2[1][1];
    }
    __syncthreads();
    if (tid < 128) sMr[tid] = fmaxf(sP0[tid], sP1[tid]);
    __syncthreads();

    // ---- per-tile partial l ----
    float mrow[2][2];
    #pragma unroll
    for (int mt = 0; mt < 2; mt++) {
        mrow[mt][0] = sMr[qrow0 + mt * 16 + er];
        mrow[mt][1] = sMr[qrow0 + mt * 16 + er + 8];
    }
    #pragma unroll
    for (int mt = 0; mt < 2; mt++) {
        float s0 = 0.0f, s1 = 0.0f;
        #pragma unroll
        for (int nb = 0; nb < 8; nb++) {
            s0 += __expf(acc[mt][nb][0] - mrow[mt][0]) + __expf(acc[mt][nb][1] - mrow[mt][0]);
            s1 += __expf(acc[mt][nb][2] - mrow[mt][1]) + __expf(acc[mt][nb][3] - mrow[mt][1]);
        }
        s0 += __shfl_xor_sync(0xffffffffu, s0, 1);
        s0 += __shfl_xor_sync(0xffffffffu, s0, 2);
        s1 += __shfl_xor_sync(0xffffffffu, s1, 1);
        s1 += __shfl_xor_sync(0xffffffffu, s1, 2);
        rr2[mt][0] = s0; rr2[mt][1] = s1;
    }
    if ((lane & 3) == 0) {
        sP[qrow0 + er]      = rr2[0][0];
        sP[qrow0 + er + 8]  = rr2[0][1];
        sP[qrow0 + er + 16] = rr2[1][0];
        sP[qrow0 + er + 24] = rr2[1][1];
    }
    __syncthreads();
    if (tid < 128) {
        const size_t pidx = (((size_t)bh * 16 + qt) * 16 + kc) * 128 + tid;
        g_pm[pidx] = sMr[tid];
        g_pl[pidx] = sP0[tid] + sP1[tid];
    }

    // ---- raw scores to gmem ----
    float* dst = g_sc + ((size_t)bh * S + q0 + qrow0) * S + k0 + kcol0;
    #pragma unroll
    for (int mt = 0; mt < 2; mt++)
        #pragma unroll
        for (int nb = 0; nb < 8; nb++) {
            *(float2*)(dst + (size_t)(mt * 16 + er) * S + nb * 8 + ec) =
                make_float2(acc[mt][nb][0], acc[mt][nb][1]);
            *(float2*)(dst + (size_t)(mt * 16 + er + 8) * S + nb * 8 + ec) =
                make_float2(acc[mt][nb][2], acc[mt][nb][3]);
        }
}

// ---------------------------------------------------------------------------
// Kernel 3: softmax + mask-apply + fp16 + PV.  CTA: 128q x one bh; 8 warps.
// ---------------------------------------------------------------------------
__global__ __launch_bounds__(256, 2) void pv_kernel(float* __restrict__ out)
{
    extern __shared__ char smraw[];
    __half* sVH = (__half*)smraw;            // [64][PADV]
    __half* sVL = sVH + 64 * PADV;
    __half* sAT = sVL + 64 * PADV;           // [128][PADV]
    float*  sM  = (float*)(sAT + 128 * PADV);// [128]
    float*  sInv = sM + 128;                 // [128]

    const int tid = threadIdx.x;
    const int qt = blockIdx.x, bh = blockIdx.y;
    const int q0 = qt * 128;

    if (tid < 128) {
        const size_t pbase = (((size_t)bh * 16 + qt) * 16) * 128 + tid;
        float m = -1e30f;
        float pm[16];
        #pragma unroll
        for (int t = 0; t < 16; t++) { pm[t] = g_pm[pbase + t * 128]; m = fmaxf(m, pm[t]); }
        float l = 0.0f;
        #pragma unroll
        for (int t = 0; t < 16; t++) l += g_pl[pbase + t * 128] * __expf(pm[t] - m);
        sM[tid] = m;
        sInv[tid] = (1.0f / l) * (1.0f / 0.9f);   // fold dropout scale
    }
    __syncthreads();

    const int w = tid >> 5, lane = tid & 31;
    const int qrow0 = (w >> 1) * 32, kcol0 = (w & 1) * 64;
    const int lr = lane & 7, lg = lane >> 3;
    const int er = lane >> 2, ec = (lane & 3) * 2;

    const int ecol0 = (w & 1) * 32;
    const int parow = qrow0 + lr + (lg & 1) * 8;
    const int pacol = (lg >> 1) * 8;
    const int pbrow = ecol0 + lr + (lg >> 1) * 8;
    const int pbcol = (lg & 1) * 8;

    const uint32_t uVH = smem_to_u32(sVH), uVL = smem_to_u32(sVL);
    const uint32_t uAT = smem_to_u32(sAT);

    const __half* vhp = g_vh + (size_t)bh * 64 * S;
    const __half* vlp = g_vl + (size_t)bh * 64 * S;

    const float m0 = sM[qrow0 + er],          i0 = sInv[qrow0 + er];
    const float m1 = sM[qrow0 + er + 8],      i1 = sInv[qrow0 + er + 8];
    const float m2 = sM[qrow0 + 16 + er],     i2 = sInv[qrow0 + 16 + er];
    const float m3 = sM[qrow0 + 16 + er + 8], i3 = sInv[qrow0 + 16 + er + 8];

    const float* sr0 = g_sc + ((size_t)bh * S + q0 + qrow0 + er) * S;
    const float* sr1 = sr0 + (size_t)8 * S;
    const float* sr2 = sr0 + (size_t)16 * S;
    const float* sr3 = sr0 + (size_t)24 * S;

    const uint32_t* mk0 = g_mask + (size_t)(bh * S + q0 + qrow0 + er) * 64 + (kcol0 >> 5);
    const uint32_t* mk1 = mk0 + (size_t)8 * 64;
    const uint32_t* mk2 = mk0 + (size_t)16 * 64;
    const uint32_t* mk3 = mk0 + (size_t)24 * 64;

    float oacc[2][4][4];
    #pragma unroll
    for (int i = 0; i < 2; i++)
        #pragma unroll
        for (int j = 0; j < 4; j++)
            #pragma unroll
            for (int l = 0; l < 4; l++) oacc[i][j][l] = 0.0f;

    for (int c = 0; c < 16; c++) {
        for (int i = tid; i < 1024; i += 256) {
            int r = i >> 4, cc = (i & 15) * 8;
            *(uint4*)(sVH + r * PADV + cc) = *(const uint4*)(vhp + (size_t)r * S + c * 128 + cc);
            *(uint4*)(sVL + r * PADV + cc) = *(const uint4*)(vlp + (size_t)r * S + c * 128 + cc);
        }

        const uint2 wm0 = *(const uint2*)(mk0 + c * 4);
        const uint2 wm1 = *(const uint2*)(mk1 + c * 4);
        const uint2 wm2 = *(const uint2*)(mk2 + c * 4);
        const uint2 wm3 = *(const uint2*)(mk3 + c * 4);

        #pragma unroll
        for (int nb = 0; nb < 8; nb++) {
            const int col = c * 128 + kcol0 + nb * 8 + ec;
            float2 v0 = *(const float2*)(sr0 + col);
            float2 v1 = *(const float2*)(sr1 + col);
            float2 v2 = *(const float2*)(sr2 + col);
            float2 v3 = *(const float2*)(sr3 + col);

            float t0a = __expf(v0.x - m0) * i0, t0b = __expf(v0.y - m0) * i0;
            float t1a = __expf(v1.x - m1) * i1, t1b = __expf(v1.y - m1) * i1;
            float t2a = __expf(v2.x - m2) * i2, t2b = __expf(v2.y - m2) * i2;
            float t3a = __expf(v3.x - m3) * i3, t3b = __expf(v3.y - m3) * i3;

            const int sh = (nb & 3) * 8 + ec;
            const uint32_t u0 = (nb < 4) ? wm0.x : wm0.y;
            const uint32_t u1 = (nb < 4) ? wm1.x : wm1.y;
            const uint32_t u2 = (nb < 4) ? wm2.x : wm2.y;
            const uint32_t u3 = (nb < 4) ? wm3.x : wm3.y;
            t0a = ((u0 >> sh) & 1u) ? t0a : 0.0f;
            t0b = ((u0 >> (sh + 1)) & 1u) ? t0b : 0.0f;
            t1a = ((u1 >> sh) & 1u) ? t1a : 0.0f;
            t1b = ((u1 >> (sh + 1)) & 1u) ? t1b : 0.0f;
            t2a = ((u2 >> sh) & 1u) ? t2a : 0.0f;
            t2b = ((u2 >> (sh + 1)) & 1u) ? t2b : 0.0f;
            t3a = ((u3 >> sh) & 1u) ? t3a : 0.0f;
            t3b = ((u3 >> (sh + 1)) & 1u) ? t3b : 0.0f;

            const int scol = kcol0 + nb * 8 + ec;
            *(uint32_t*)(sAT + (qrow0 + er) * PADV + scol) =
                (uint32_t)__half_as_ushort(__float2half_rn(t0a)) |
                ((uint32_t)__half_as_ushort(__float2half_rn(t0b)) << 16);
            *(uint32_t*)(sAT + (qrow0 + er + 8) * PADV + scol) =
                (uint32_t)__half_as_ushort(__float2half_rn(t1a)) |
                ((uint32_t)__half_as_ushort(__float2half_rn(t1b)) << 16);
            *(uint32_t*)(sAT + (qrow0 + 16 + er) * PADV + scol) =
                (uint32_t)__half_as_ushort(__float2half_rn(t2a)) |
                ((uint32_t)__half_as_ushort(__float2half_rn(t2b)) << 16);
            *(uint32_t*)(sAT + (qrow0 + 16 + er + 8) * PADV + scol) =
                (uint32_t)__half_as_ushort(__float2half_rn(t3a)) |
                ((uint32_t)__half_as_ushort(__float2half_rn(t3b)) << 16);
        }
        __syncthreads();

        #pragma unroll
        for (int ks = 0; ks < 8; ks++) {
            uint32_t a[2][4];
            #pragma unroll
            for (int mt = 0; mt < 2; mt++)
                LDSM_X4(a[mt][0], a[mt][1], a[mt][2], a[mt][3],
                        uAT + (uint32_t)(((parow + mt * 16) * PADV + pacol + ks * 16) * 2));
            uint32_t bh2[2][4], bl2[2][4];
            #pragma unroll
            for (int nbp = 0; nbp < 2; nbp++) {
                LDSM_X4(bh2[nbp][0], bh2[nbp][1], bh2[nbp][2], bh2[nbp][3],
                        uVH + (uint32_t)(((pbrow + nbp * 16) * PADV + pbcol + ks * 16) * 2));
                LDSM_X4(bl2[nbp][0], bl2[nbp][1], bl2[nbp][2], bl2[nbp][3],
                        uVL + (uint32_t)(((pbrow + nbp * 16) * PADV + pbcol + ks * 16) * 2));
            }
            #pragma unroll
            for (int mt = 0; mt < 2; mt++)
                #pragma unroll
                for (int nb = 0; nb < 4; nb++) {
                    MMA16816(oacc[mt][nb], a[mt][0], a[mt][1], a[mt][2], a[mt][3],
                             bh2[nb >> 1][(nb & 1) * 2], bh2[nb >> 1][(nb & 1) * 2 + 1]);
                    MMA16816(oacc[mt][nb], a[mt][0], a[mt][1], a[mt][2], a[mt][3],
                             bl2[nb >> 1][(nb & 1) * 2], bl2[nb >> 1][(nb & 1) * 2 + 1]);
                }
        }
        __syncthreads();
    }

    float* dst = out + ((size_t)bh * S + q0 + qrow0) * 64 + ecol0;
    #pragma unroll
    for (int mt = 0; mt < 2; mt++)
        #pragma unroll
        for (int nb = 0; nb < 4; nb++) {
            *(float2*)(dst + (size_t)(mt * 16 + er) * 64 + nb * 8 + ec) =
                make_float2(oacc[mt][nb][0], oacc[mt][nb][1]);
            *(float2*)(dst + (size_t)(mt * 16 + er + 8) * 64 + nb * 8 + ec) =
                make_float2(oacc[mt][nb][2], oacc[mt][nb][3]);
        }
}

// ---------------------------------------------------------------------------
extern "C" void kernel_launch(void* const* d_in, const int* in_sizes, int n_in,
                              void* d_out, int out_size) {
    (void)in_sizes; (void)n_in; (void)out_size;
    const float* query = (const float*)d_in[0];
    const float* key   = (const float*)d_in[1];
    const float* value = (const float*)d_in[2];
    const float* Wq    = (const float*)d_in[3];
    const float* bq    = (const float*)d_in[4];
    const float* Wk    = (const float*)d_in[5];
    const float* bk    = (const float*)d_in[6];
    const float* Wv    = (const float*)d_in[7];
    const float* bv    = (const float*)d_in[8];
    float* out = (float*)d_out;

    const int sc_smem = 4 * 128 * PADQ * 2 + 3 * 128 * 4;
    const int pv_smem = (2 * 64 * PADV + 128 * PADV) * 2 + 2 * 128 * 4;

    cudaFuncSetAttribute(proj_kernel,   cudaFuncAttributeMaxDynamicSharedMemorySize, PROJ_SMEM);
    cudaFuncSetAttribute(scores_kernel, cudaFuncAttributeMaxDynamicSharedMemorySize, sc_smem);
    cudaFuncSetAttribute(pv_kernel,     cudaFuncAttributeMaxDynamicSharedMemorySize, pv_smem);

    dim3 pg(S / 128, BH, 3);
    proj_kernel<<<pg, 256, PROJ_SMEM>>>(query, key, value, Wq, bq, Wk, bk, Wv, bv);

    dim3 sg(S / 128, S / 128, BH);
    scores_kernel<<<sg, 256, sc_smem>>>();

    dim3 ag(S / 128, BH);
    pv_kernel<<<ag, 256, pv_smem>>>(out);
}

// round 7
// speedup vs baseline: 1.4307x; 1.1108x over previous
#include <cuda_runtime.h>
#include <cuda_fp16.h>
#include <stdint.h>

#define B 4
#define S 2048
#define H 8
#define E 64
#define BH (B*H)
#define PADQ 72   // Q/K smem row stride (halves)
#define PADT 72   // pv smem row stride (halves)

// ---------------------------------------------------------------------------
// Device scratch (allocation-free)
// ---------------------------------------------------------------------------
__device__ __half g_qh[(size_t)BH*S*E];   // fp16 hi of 0.125*Qproj [bh][s][e]
__device__ __half g_ql[(size_t)BH*S*E];
__device__ __half g_kh[(size_t)BH*S*E];   // [bh][s][e]
__device__ __half g_kl[(size_t)BH*S*E];
__device__ __half g_vh[(size_t)BH*E*S];   // transposed [bh][e][s]
__device__ __half g_vl[(size_t)BH*E*S];
__device__ float  g_sc[(size_t)BH*S*S];   // raw fp32 scores [bh][q][k]
__device__ float  g_pm[(size_t)BH*16*32*128];  // per-tile row max   [bh][qt][kc64][r]
__device__ float  g_pl[(size_t)BH*16*32*128];  // per-tile partial l
__device__ uint32_t g_mask[(size_t)BH*S*64];   // keep-bits (even 64-tiles only)

// ---------------------------------------------------------------------------
// MMA helpers (baseline PTX, works at .target sm_103)
// ---------------------------------------------------------------------------
__device__ __forceinline__ uint32_t smem_to_u32(const void* p) {
    uint32_t a;
    asm("{ .reg .u64 t; cvta.to.shared.u64 t, %1; cvt.u32.u64 %0, t; }" : "=r"(a) : "l"(p));
    return a;
}
#define LDSM_X4(R0, R1, R2, R3, ADDR) \
    asm volatile("ldmatrix.sync.aligned.m8n8.x4.shared.b16 {%0,%1,%2,%3}, [%4];" \
                 : "=r"(R0), "=r"(R1), "=r"(R2), "=r"(R3) : "r"(ADDR))
#define MMA16816(C, A0, A1, A2, A3, B0, B1) \
    asm volatile("mma.sync.aligned.m16n8k16.row.col.f32.f16.f16.f32 " \
                 "{%0,%1,%2,%3}, {%4,%5,%6,%7}, {%8,%9}, {%0,%1,%2,%3};" \
                 : "+f"((C)[0]), "+f"((C)[1]), "+f"((C)[2]), "+f"((C)[3]) \
                 : "r"(A0), "r"(A1), "r"(A2), "r"(A3), "r"(B0), "r"(B1))

// ---------------------------------------------------------------------------
// Threefry2x32 (JAX partitionable) — validated rounds 1/3/4/5/6
// ---------------------------------------------------------------------------
__device__ __forceinline__ uint32_t rotl32(uint32_t v, int s) { return __funnelshift_l(v, v, s); }
__device__ __forceinline__ uint32_t threefry_mask_bits(uint32_t idx) {
    const uint32_t ks0 = 0u, ks1 = 42u, ks2 = 0x1BD11BDAu ^ 42u;
    uint32_t x0 = ks0, x1 = idx + ks1;
#define TFR(r) { x0 += x1; x1 = rotl32(x1, r); x1 ^= x0; }
    TFR(13) TFR(15) TFR(26) TFR(6)
    x0 += ks1; x1 += ks2 + 1u;
    TFR(17) TFR(29) TFR(16) TFR(24)
    x0 += ks2; x1 += ks0 + 2u;
    TFR(13) TFR(15) TFR(26) TFR(6)
    x0 += ks0; x1 += ks1 + 3u;
    TFR(17) TFR(29) TFR(16) TFR(24)
    x0 += ks1; x1 += ks2 + 4u;
    TFR(13) TFR(15) TFR(26) TFR(6)
    x0 += ks2; x1 += ks0 + 5u;
#undef TFR
    return x0 ^ x1;
}
#define KEEP_THRESH (7549747u << 9)

// ---------------------------------------------------------------------------
// Kernel 1: QKV projection.  occ 3: no reg weight cache, half-size V buffer.
// ---------------------------------------------------------------------------
#define SYW 65  // sY stride (uint32)

__global__ __launch_bounds__(256, 3) void proj_kernel(
    const float* __restrict__ qin, const float* __restrict__ kin, const float* __restrict__ vin,
    const float* __restrict__ Wq, const float* __restrict__ bq,
    const float* __restrict__ Wk, const float* __restrict__ bk,
    const float* __restrict__ Wv, const float* __restrict__ bv)
{
    extern __shared__ char dyn[];
    float* sW = (float*)dyn;                 // [64][68]
    float* sbv = sW + 64 * 68;               // [64]
    float* sx = sbv + 64;                    // [128][64]
    uint32_t* sY = (uint32_t*)(sx + 128*64); // [64][SYW]  (V only, per 64-s half)

    const int tid = threadIdx.x;
    const int s0 = blockIdx.x * 128;
    const int bh = blockIdx.y;
    const int m  = blockIdx.z;
    const int b = bh >> 3, h = bh & 7;

    const float* __restrict__ xin  = (m == 0) ? qin : ((m == 1) ? kin : vin);
    const float* __restrict__ W    = (m == 0) ? Wq  : ((m == 1) ? Wk  : Wv);
    const float* __restrict__ bias = (m == 0) ? bq  : ((m == 1) ? bk  : bv);

    for (int i = tid; i < 64 * 16; i += 256) {
        int r = i >> 4, c = i & 15;
        ((float4*)(sW + r * 68))[c] = ((const float4*)W)[i];
    }
    if (tid < 64) sbv[tid] = bias[tid];
    for (int i = tid; i < 128 * 16; i += 256) {
        int s = i >> 4, c = i & 15;
        ((float4*)(sx + s * 64))[c] =
            ((const float4*)(xin + ((size_t)((b * S + s0 + s) * H + h)) * 64))[c];
    }
    __syncthreads();

    const int f = tid & 63, sg = tid >> 6;
    const float bf = sbv[f];

    if (m < 2) {
        const float qs = (m == 0) ? 0.125f : 1.0f;
        __half* dh = ((m == 0) ? g_qh : g_kh) + ((size_t)bh * S + s0) * 64 + f;
        __half* dl = ((m == 0) ? g_ql : g_kl) + ((size_t)bh * S + s0) * 64 + f;
        #pragma unroll 2
        for (int ss = 0; ss < 32; ss++) {
            const int s = sg * 32 + ss;
            float acc = bf;
            #pragma unroll
            for (int e4 = 0; e4 < 16; e4++) {
                float4 xv = ((float4*)(sx + s * 64))[e4];
                float4 wv = ((float4*)(sW + f * 68))[e4];
                acc += xv.x * wv.x + xv.y * wv.y + xv.z * wv.z + xv.w * wv.w;
            }
            acc *= qs;
            __half hi = __float2half_rn(acc);
            __half lo = __float2half_rn(acc - __half2float(hi));
            dh[(size_t)s * 64] = hi;
            dl[(size_t)s * 64] = lo;
        }
    } else {
        for (int half = 0; half < 2; half++) {
            #pragma unroll 2
            for (int ss = 0; ss < 16; ss++) {
                const int idx = half * 16 + ss;
                const int s = sg + 4 * idx;          // warp-uniform s
                float acc = bf;
                #pragma unroll
                for (int e4 = 0; e4 < 16; e4++) {
                    float4 xv = ((float4*)(sx + s * 64))[e4];
                    float4 wv = ((float4*)(sW + f * 68))[e4];
                    acc += xv.x * wv.x + xv.y * wv.y + xv.z * wv.z + xv.w * wv.w;
                }
                __half hi = __float2half_rn(acc);
                __half lo = __float2half_rn(acc - __half2float(hi));
                sY[f * SYW + (s - half * 64)] =
                    (uint32_t)__half_as_ushort(hi) | ((uint32_t)__half_as_ushort(lo) << 16);
            }
            __syncthreads();
            for (int i = tid; i < 512; i += 256) {
                const int fr = i >> 3, c = i & 7;
                uint32_t y[8];
                #pragma unroll
                for (int j = 0; j < 8; j++) y[j] = sY[fr * SYW + c * 8 + j];
                uint4 hv, lv;
                hv.x = (y[0] & 0xffffu) | (y[1] << 16);
                hv.y = (y[2] & 0xffffu) | (y[3] << 16);
                hv.z = (y[4] & 0xffffu) | (y[5] << 16);
                hv.w = (y[6] & 0xffffu) | (y[7] << 16);
                lv.x = (y[0] >> 16) | (y[1] & 0xffff0000u);
                lv.y = (y[2] >> 16) | (y[3] & 0xffff0000u);
                lv.z = (y[4] >> 16) | (y[5] & 0xffff0000u);
                lv.w = (y[6] >> 16) | (y[7] & 0xffff0000u);
                const size_t off = ((size_t)bh * 64 + fr) * S + s0 + half * 64 + c * 8;
                *(uint4*)(g_vh + off) = hv;
                *(uint4*)(g_vl + off) = lv;
            }
            __syncthreads();
        }
    }
}
#define PROJ_SMEM ((64*68 + 64 + 128*64) * 4 + 64 * SYW * 4)

// ---------------------------------------------------------------------------
// Kernel 2: scores (128q x 64k tile) + per-tile stats + mask for EVEN tiles.
// 8 warps = 4(q) x 2(k); warp tile 32q x 32k.  occ 3.
// ---------------------------------------------------------------------------
__global__ __launch_bounds__(256, 3) void scores_kernel()
{
    extern __shared__ char smraw[];
    __half* sQH = (__half*)smraw;             // [128][PADQ]
    __half* sQL = sQH + 128 * PADQ;
    __half* sKH = sQL + 128 * PADQ;           // [64][PADQ]
    __half* sKL = sKH + 64 * PADQ;
    float*  sP0 = (float*)(sKL + 64 * PADQ);  // [128]
    float*  sP1 = sP0 + 128;
    float*  sMr = sP1 + 128;

    const int tid = threadIdx.x;
    const int kc = blockIdx.x, qt = blockIdx.y, bh = blockIdx.z;
    const int k0 = kc * 64, q0 = qt * 128;

    const __half* qhp = g_qh + ((size_t)bh * S + q0) * 64;
    const __half* qlp = g_ql + ((size_t)bh * S + q0) * 64;
    const __half* khp = g_kh + ((size_t)bh * S + k0) * 64;
    const __half* klp = g_kl + ((size_t)bh * S + k0) * 64;

    for (int i = tid; i < 1024; i += 256) {
        int r = i >> 3, c = (i & 7) * 8;
        *(uint4*)(sQH + r * PADQ + c) = *(const uint4*)(qhp + r * 64 + c);
        *(uint4*)(sQL + r * PADQ + c) = *(const uint4*)(qlp + r * 64 + c);
    }
    for (int i = tid; i < 512; i += 256) {
        int r = i >> 3, c = (i & 7) * 8;
        *(uint4*)(sKH + r * PADQ + c) = *(const uint4*)(khp + r * 64 + c);
        *(uint4*)(sKL + r * PADQ + c) = *(const uint4*)(klp + r * 64 + c);
    }
    __syncthreads();

    const int w = tid >> 5, lane = tid & 31;
    const int qrow0 = (w >> 1) * 32, kcol0 = (w & 1) * 32;
    const int lr = lane & 7, lg = lane >> 3;
    const int er = lane >> 2, ec = (lane & 3) * 2;

    const int arow = qrow0 + lr + (lg & 1) * 8;
    const int acol = (lg >> 1) * 8;
    const int brow = kcol0 + lr + (lg >> 1) * 8;
    const int bcol = (lg & 1) * 8;

    const uint32_t uQH = smem_to_u32(sQH), uQL = smem_to_u32(sQL);
    const uint32_t uKH = smem_to_u32(sKH), uKL = smem_to_u32(sKL);

    float acc[2][4][4];
    #pragma unroll
    for (int i = 0; i < 2; i++)
        #pragma unroll
        for (int j = 0; j < 4; j++)
            #pragma unroll
            for (int l = 0; l < 4; l++) acc[i][j][l] = 0.0f;

    #pragma unroll
    for (int sp = 0; sp < 3; sp++) {
        const uint32_t uA = (sp < 2) ? uQH : uQL;
        const uint32_t uB = (sp == 1) ? uKL : uKH;
        #pragma unroll
        for (int ks = 0; ks < 4; ks++) {
            uint32_t a[2][4];
            #pragma unroll
            for (int mt = 0; mt < 2; mt++)
                LDSM_X4(a[mt][0], a[mt][1], a[mt][2], a[mt][3],
                        uA + (uint32_t)(((arow + mt * 16) * PADQ + acol + ks * 16) * 2));
            uint32_t bb[2][4];
            #pragma unroll
            for (int nbp = 0; nbp < 2; nbp++)
                LDSM_X4(bb[nbp][0], bb[nbp][1], bb[nbp][2], bb[nbp][3],
                        uB + (uint32_t)(((brow + nbp * 16) * PADQ + bcol + ks * 16) * 2));
            #pragma unroll
            for (int mt = 0; mt < 2; mt++)
                #pragma unroll
                for (int nb = 0; nb < 4; nb++)
                    MMA16816(acc[mt][nb], a[mt][0], a[mt][1], a[mt][2], a[mt][3],
                             bb[nb >> 1][(nb & 1) * 2], bb[nb >> 1][(nb & 1) * 2 + 1]);
        }
    }

    // ---- dropout mask, EVEN tiles only (half the threefry load lives here) ----
    if ((kc & 1) == 0) {
        const uint32_t kbase = (uint32_t)(k0 + kcol0 + ec);
        #pragma unroll
        for (int rr = 0; rr < 4; rr++) {
            const int qg = q0 + qrow0 + (rr >> 1) * 16 + (rr & 1) * 8 + er;
            const uint32_t idxbase = (uint32_t)(bh * S + qg) * (uint32_t)S + kbase;
            uint32_t w0 = 0;
            #pragma unroll
            for (int nb = 0; nb < 4; nb++) {
                const uint32_t i0 = idxbase + nb * 8;
                uint32_t bA = (threefry_mask_bits(i0) < KEEP_THRESH) ? 1u : 0u;
                uint32_t bB = (threefry_mask_bits(i0 + 1u) < KEEP_THRESH) ? 2u : 0u;
                w0 |= (bA | bB) << (nb * 8 + ec);
            }
            w0 |= __shfl_xor_sync(0xffffffffu, w0, 1);
            w0 |= __shfl_xor_sync(0xffffffffu, w0, 2);
            if ((lane & 3) == 0)
                g_mask[(size_t)(bh * S + qg) * 64 + kc * 2 + (kcol0 >> 5)] = w0;
        }
    }

    // ---- per-tile row max ----
    float rr2[2][2];
    #pragma unroll
    for (int mt = 0; mt < 2; mt++) {
        float m0 = -1e30f, m1 = -1e30f;
        #pragma unroll
        for (int nb = 0; nb < 4; nb++) {
            m0 = fmaxf(m0, fmaxf(acc[mt][nb][0], acc[mt][nb][1]));
            m1 = fmaxf(m1, fmaxf(acc[mt][nb][2], acc[mt][nb][3]));
        }
        m0 = fmaxf(m0, __shfl_xor_sync(0xffffffffu, m0, 1));
        m0 = fmaxf(m0, __shfl_xor_sync(0xffffffffu, m0, 2));
        m1 = fmaxf(m1, __shfl_xor_sync(0xffffffffu, m1, 1));
        m1 = fmaxf(m1, __shfl_xor_sync(0xffffffffu, m1, 2));
        rr2[mt][0] = m0; rr2[mt][1] = m1;
    }
    float* sP = (w & 1) ? sP1 : sP0;
    if ((lane & 3) == 0) {
        sP[qrow0 + er]      = rr2[0][0];
        sP[qrow0 + er + 8]  = rr2[0][1];
        sP[qrow0 + er + 16] = rr2[1][0];
        sP[qrow0 + er + 24] = rr2[1][1];
    }
    __syncthreads();
    if (tid < 128) sMr[tid] = fmaxf(sP0[tid], sP1[tid]);
    __syncthreads();

    // ---- per-tile partial l ----
    float mrow[2][2];
    #pragma unroll
    for (int mt = 0; mt < 2; mt++) {
        mrow[mt][0] = sMr[qrow0 + mt * 16 + er];
        mrow[mt][1] = sMr[qrow0 + mt * 16 + er + 8];
    }
    #pragma unroll
    for (int mt = 0; mt < 2; mt++) {
        float s0 = 0.0f, s1 = 0.0f;
        #pragma unroll
        for (int nb = 0; nb < 4; nb++) {
            s0 += __expf(acc[mt][nb][0] - mrow[mt][0]) + __expf(acc[mt][nb][1] - mrow[mt][0]);
            s1 += __expf(acc[mt][nb][2] - mrow[mt][1]) + __expf(acc[mt][nb][3] - mrow[mt][1]);
        }
        s0 += __shfl_xor_sync(0xffffffffu, s0, 1);
        s0 += __shfl_xor_sync(0xffffffffu, s0, 2);
        s1 += __shfl_xor_sync(0xffffffffu, s1, 1);
        s1 += __shfl_xor_sync(0xffffffffu, s1, 2);
        rr2[mt][0] = s0; rr2[mt][1] = s1;
    }
    if ((lane & 3) == 0) {
        sP[qrow0 + er]      = rr2[0][0];
        sP[qrow0 + er + 8]  = rr2[0][1];
        sP[qrow0 + er + 16] = rr2[1][0];
        sP[qrow0 + er + 24] = rr2[1][1];
    }
    __syncthreads();
    if (tid < 128) {
        const size_t pidx = (((size_t)bh * 16 + qt) * 32 + kc) * 128 + tid;
        g_pm[pidx] = sMr[tid];
        g_pl[pidx] = sP0[tid] + sP1[tid];
    }

    // ---- raw scores to gmem ----
    float* dst = g_sc + ((size_t)bh * S + q0 + qrow0) * S + k0 + kcol0;
    #pragma unroll
    for (int mt = 0; mt < 2; mt++)
        #pragma unroll
        for (int nb = 0; nb < 4; nb++) {
            *(float2*)(dst + (size_t)(mt * 16 + er) * S + nb * 8 + ec) =
                make_float2(acc[mt][nb][0], acc[mt][nb][1]);
            *(float2*)(dst + (size_t)(mt * 16 + er + 8) * S + nb * 8 + ec) =
                make_float2(acc[mt][nb][2], acc[mt][nb][3]);
        }
}
#define SC_SMEM ((128*2 + 64*2) * PADQ * 2 + 3 * 128 * 4)

// ---------------------------------------------------------------------------
// Kernel 3: softmax + dropout (half load / half compute) + fp16 + PV.
// CTA: 64q x one bh; 64-wide k chunks; 8 warps = 2(q) x 4(e).  occ 4.
// ---------------------------------------------------------------------------
__global__ __launch_bounds__(256, 4) void pv_kernel(float* __restrict__ out)
{
    extern __shared__ char smraw[];
    __half* sVH = (__half*)smraw;             // [64][PADT]
    __half* sVL = sVH + 64 * PADT;
    __half* sAT = sVL + 64 * PADT;            // [64][PADT]
    float*  sM  = (float*)(sAT + 64 * PADT);  // [64]
    float*  sInv = sM + 64;                   // [64]

    const int tid = threadIdx.x;
    const int q0 = blockIdx.x * 64, bh = blockIdx.y;

    // combine per-tile stats (32 tiles of width 64)
    if (tid < 64) {
        const int qt128 = q0 >> 7;
        const int r128 = (q0 & 127) + tid;
        const size_t pb = (((size_t)bh * 16 + qt128) * 32) * 128 + r128;
        float m = -1e30f;
        for (int t = 0; t < 32; t++) m = fmaxf(m, g_pm[pb + t * 128]);
        float l = 0.0f;
        for (int t = 0; t < 32; t++) l += g_pl[pb + t * 128] * __expf(g_pm[pb + t * 128] - m);
        sM[tid] = m;
        sInv[tid] = (1.0f / l) * (1.0f / 0.9f);
    }
    __syncthreads();

    const int w = tid >> 5, lane = tid & 31;
    const int qrow0 = (w >> 2) * 32, ecol0 = (w & 3) * 16;
    const int lr = lane & 7, lg = lane >> 3;
    const int er = lane >> 2, ec = (lane & 3) * 2;

    const int arow = qrow0 + lr + (lg & 1) * 8;
    const int acol = (lg >> 1) * 8;
    const int brow = ecol0 + lr + (lg >> 1) * 8;
    const int bcol = (lg & 1) * 8;

    const uint32_t uVH = smem_to_u32(sVH), uVL = smem_to_u32(sVL);
    const uint32_t uAT = smem_to_u32(sAT);

    const __half* vhp = g_vh + (size_t)bh * 64 * S;
    const __half* vlp = g_vl + (size_t)bh * 64 * S;

    // softmax-stage mapping: 4 threads per row, 16 cols each
    const int row = tid >> 2;
    const int cb  = (tid & 3) * 16;
    const float mrow = sM[row], inv = sInv[row];
    const float* srow = g_sc + ((size_t)(bh * S + q0 + row)) * S;
    const uint32_t ib = (uint32_t)((bh * S + q0 + row) * S);
    const uint32_t* mrow_ptr = g_mask + (size_t)(bh * S + q0 + row) * 64;

    float oacc[2][2][4];
    #pragma unroll
    for (int i = 0; i < 2; i++)
        #pragma unroll
        for (int j = 0; j < 2; j++)
            #pragma unroll
            for (int l = 0; l < 4; l++) oacc[i][j][l] = 0.0f;

    for (int c = 0; c < 32; c++) {
        // V chunk -> smem
        for (int i = tid; i < 512; i += 256) {
            int r = i >> 3, cc = (i & 7) * 8;
            *(uint4*)(sVH + r * PADT + cc) = *(const uint4*)(vhp + (size_t)r * S + c * 64 + cc);
            *(uint4*)(sVL + r * PADT + cc) = *(const uint4*)(vlp + (size_t)r * S + c * 64 + cc);
        }

        // attn tile (16 elements per thread)
        const int col0 = c * 64 + cb;
        float4 v[4];
        v[0] = *(const float4*)(srow + col0);
        v[1] = *(const float4*)(srow + col0 + 4);
        v[2] = *(const float4*)(srow + col0 + 8);
        v[3] = *(const float4*)(srow + col0 + 12);

        uint32_t keepbits;
        if ((c & 1) == 0) {
            keepbits = mrow_ptr[c * 2 + (cb >> 5)] >> (cb & 16);
        } else {
            keepbits = 0;
            #pragma unroll
            for (int j = 0; j < 16; j++)
                keepbits |= (threefry_mask_bits(ib + col0 + j) < KEEP_THRESH) ? (1u << j) : 0u;
        }

        uint32_t* dstw = (uint32_t*)(sAT + row * PADT + cb);
        #pragma unroll
        for (int jj = 0; jj < 8; jj++) {
            float sa = ((const float*)v)[jj * 2];
            float sb = ((const float*)v)[jj * 2 + 1];
            float ta = __expf(sa - mrow) * inv;
            float tb = __expf(sb - mrow) * inv;
            ta = ((keepbits >> (jj * 2)) & 1u) ? ta : 0.0f;
            tb = ((keepbits >> (jj * 2 + 1)) & 1u) ? tb : 0.0f;
            dstw[jj] = (uint32_t)__half_as_ushort(__float2half_rn(ta)) |
                       ((uint32_t)__half_as_ushort(__float2half_rn(tb)) << 16);
        }
        __syncthreads();

        // PV MMA (warp tile 32q x 16e, k=64)
        #pragma unroll
        for (int ks = 0; ks < 4; ks++) {
            uint32_t a[2][4];
            #pragma unroll
            for (int mt = 0; mt < 2; mt++)
                LDSM_X4(a[mt][0], a[mt][1], a[mt][2], a[mt][3],
                        uAT + (uint32_t)(((arow + mt * 16) * PADT + acol + ks * 16) * 2));
            uint32_t bhf[4], blf[4];
            LDSM_X4(bhf[0], bhf[1], bhf[2], bhf[3],
                    uVH + (uint32_t)((brow * PADT + bcol + ks * 16) * 2));
            LDSM_X4(blf[0], blf[1], blf[2], blf[3],
                    uVL + (uint32_t)((brow * PADT + bcol + ks * 16) * 2));
            #pragma unroll
            for (int mt = 0; mt < 2; mt++)
                #pragma unroll
                for (int nb = 0; nb < 2; nb++) {
                    MMA16816(oacc[mt][nb], a[mt][0], a[mt][1], a[mt][2], a[mt][3],
                             bhf[nb * 2], bhf[nb * 2 + 1]);
                    MMA16816(oacc[mt][nb], a[mt][0], a[mt][1], a[mt][2], a[mt][3],
                             blf[nb * 2], blf[nb * 2 + 1]);
                }
        }
        __syncthreads();
    }

    float* dst = out + ((size_t)bh * S + q0 + qrow0) * 64 + ecol0;
    #pragma unroll
    for (int mt = 0; mt < 2; mt++)
        #pragma unroll
        for (int nb = 0; nb < 2; nb++) {
            *(float2*)(dst + (size_t)(mt * 16 + er) * 64 + nb * 8 + ec) =
                make_float2(oacc[mt][nb][0], oacc[mt][nb][1]);
            *(float2*)(dst + (size_t)(mt * 16 + er + 8) * 64 + nb * 8 + ec) =
                make_float2(oacc[mt][nb][2], oacc[mt][nb][3]);
        }
}
#define PV_SMEM (3 * 64 * PADT * 2 + 2 * 64 * 4)

// ---------------------------------------------------------------------------
extern "C" void kernel_launch(void* const* d_in, const int* in_sizes, int n_in,
                              void* d_out, int out_size) {
    (void)in_sizes; (void)n_in; (void)out_size;
    const float* query = (const float*)d_in[0];
    const float* key   = (const float*)d_in[1];
    const float* value = (const float*)d_in[2];
    const float* Wq    = (const float*)d_in[3];
    const float* bq    = (const float*)d_in[4];
    const float* Wk    = (const float*)d_in[5];
    const float* bk    = (const float*)d_in[6];
    const float* Wv    = (const float*)d_in[7];
    const float* bv    = (const float*)d_in[8];
    float* out = (float*)d_out;

    cudaFuncSetAttribute(proj_kernel,   cudaFuncAttributeMaxDynamicSharedMemorySize, PROJ_SMEM);
    cudaFuncSetAttribute(scores_kernel, cudaFuncAttributeMaxDynamicSharedMemorySize, SC_SMEM);
    cudaFuncSetAttribute(pv_kernel,     cudaFuncAttributeMaxDynamicSharedMemorySize, PV_SMEM);

    dim3 pg(S / 128, BH, 3);
    proj_kernel<<<pg, 256, PROJ_SMEM>>>(query, key, value, Wq, bq, Wk, bk, Wv, bv);

    dim3 sg(S / 64, S / 128, BH);
    scores_kernel<<<sg, 256, SC_SMEM>>>();

    dim3 ag(S / 64, BH);
    pv_kernel<<<ag, 256, PV_SMEM>>>(out);
}